// round 1
// baseline (speedup 1.0000x reference)
#include <cuda_runtime.h>
#include <math.h>
#include <stdint.h>

// ---------------------------------------------------------------------------
// Problem constants
// ---------------------------------------------------------------------------
namespace {
constexpr int B_ = 8, S_ = 512, C_ = 12, D_ = 512, H_ = 8, F_ = 2048, L_ = 4;
constexpr int DK_ = D_ / H_;          // 64
constexpr int T_  = B_ * S_;          // 4096 tokens
constexpr float EPS_ = 1e-5f;
constexpr float SCALE_ = 0.125f;      // 1/sqrt(64)
}

// ---------------------------------------------------------------------------
// Scratch (static device globals -- no allocations allowed)
// ---------------------------------------------------------------------------
__device__ float g_x  [T_ * D_];
__device__ float g_q  [T_ * D_];
__device__ float g_k  [T_ * D_];
__device__ float g_v  [T_ * D_];
__device__ float g_ctx[T_ * D_];
__device__ float g_tmp[T_ * D_];
__device__ float g_ffn[T_ * F_];

// ---------------------------------------------------------------------------
// Embedding: x = enc @ val_w + val_b + pos    (K = 12, trivially small)
// ---------------------------------------------------------------------------
__global__ void embed_kernel(const float* __restrict__ enc,
                             const float* __restrict__ vw,
                             const float* __restrict__ vb,
                             const float* __restrict__ pos,
                             float* __restrict__ x) {
    int idx = blockIdx.x * blockDim.x + threadIdx.x;
    if (idx >= T_ * D_) return;
    int t = idx >> 9;          // / 512
    int d = idx & (D_ - 1);
    int s = t & (S_ - 1);
    float acc = vb[d] + pos[s * D_ + d];
    const float* e = enc + t * C_;
#pragma unroll
    for (int c = 0; c < C_; c++) acc = fmaf(e[c], vw[c * D_ + d], acc);
    x[idx] = acc;
}

// ---------------------------------------------------------------------------
// Reductions
// ---------------------------------------------------------------------------
__device__ __forceinline__ float warpReduceSum(float v) {
#pragma unroll
    for (int o = 16; o > 0; o >>= 1) v += __shfl_xor_sync(0xffffffffu, v, o);
    return v;
}
__device__ __forceinline__ float warpReduceMax(float v) {
#pragma unroll
    for (int o = 16; o > 0; o >>= 1) v = fmaxf(v, __shfl_xor_sync(0xffffffffu, v, o));
    return v;
}
// blockDim.x == 256 (8 warps) assumed
__device__ __forceinline__ float blockReduceSum(float v, float* sh) {
    int lane = threadIdx.x & 31, wid = threadIdx.x >> 5;
    v = warpReduceSum(v);
    __syncthreads();
    if (lane == 0) sh[wid] = v;
    __syncthreads();
    if (wid == 0) {
        float t = (lane < 8) ? sh[lane] : 0.f;
        t = warpReduceSum(t);
        if (lane == 0) sh[0] = t;
    }
    __syncthreads();
    return sh[0];
}
__device__ __forceinline__ float blockReduceMax(float v, float* sh) {
    int lane = threadIdx.x & 31, wid = threadIdx.x >> 5;
    v = warpReduceMax(v);
    __syncthreads();
    if (lane == 0) sh[wid] = v;
    __syncthreads();
    if (wid == 0) {
        float t = (lane < 8) ? sh[lane] : -INFINITY;
        t = warpReduceMax(t);
        if (lane == 0) sh[0] = t;
    }
    __syncthreads();
    return sh[0];
}

// ---------------------------------------------------------------------------
// Softmax over rows of length 512, in place. grid = numRows, block = 256.
// ---------------------------------------------------------------------------
__global__ void softmax512_kernel(float* __restrict__ data) {
    __shared__ float sh[32];
    float* p = data + (size_t)blockIdx.x * 512;
    int t = threadIdx.x;
    float v0 = p[t], v1 = p[t + 256];
    float m = blockReduceMax(fmaxf(v0, v1), sh);
    float e0 = expf(v0 - m), e1 = expf(v1 - m);
    float s = blockReduceSum(e0 + e1, sh);
    float inv = 1.f / s;
    p[t]       = e0 * inv;
    p[t + 256] = e1 * inv;
}

// ---------------------------------------------------------------------------
// Residual add + LayerNorm: x = LN(y + x) * g + b. Row length 512. block=256.
// ---------------------------------------------------------------------------
__global__ void ln_residual_kernel(const float* __restrict__ y,
                                   float* __restrict__ x,
                                   const float* __restrict__ g,
                                   const float* __restrict__ b) {
    __shared__ float sh[32];
    size_t base = (size_t)blockIdx.x * 512;
    int t = threadIdx.x;
    float s0 = y[base + t]       + x[base + t];
    float s1 = y[base + t + 256] + x[base + t + 256];
    float mean = blockReduceSum(s0 + s1, sh) * (1.f / 512.f);
    float d0 = s0 - mean, d1 = s1 - mean;
    float var = blockReduceSum(d0 * d0 + d1 * d1, sh) * (1.f / 512.f);
    float rs = rsqrtf(var + EPS_);
    x[base + t]       = d0 * rs * g[t]       + b[t];
    x[base + t + 256] = d1 * rs * g[t + 256] + b[t + 256];
}

// ---------------------------------------------------------------------------
// Tiled batched-strided SGEMM.
//   C = alpha * A @ op(B) + bias(+relu)
// A: [M,K] row-major (lda). B: non-trans [K,N] (ldb) or trans [N,K] (ldb).
// Batch z: off = (z / bH) * Outer + (z % bH) * Inner, per operand.
// Requires: (BM/TM)*(BN/TN) == 256 threads, BM*BK == BK*BN == 1024 elems.
// ---------------------------------------------------------------------------
template <int BM, int BN, int BK, int TM, int TN, bool TB>
__global__ __launch_bounds__(256) void gemm_kernel(
    const float* __restrict__ Ag, const float* __restrict__ Bg,
    float* __restrict__ Cg, const float* __restrict__ bias,
    int M, int N, int K, int lda, int ldb, int ldc,
    long aO, long aI, long bO, long bI, long cO, long cI, int bH,
    float alpha, int relu) {
    int z = blockIdx.z;
    Ag += (long)(z / bH) * aO + (long)(z % bH) * aI;
    Bg += (long)(z / bH) * bO + (long)(z % bH) * bI;
    Cg += (long)(z / bH) * cO + (long)(z % bH) * cI;

    const int tid = threadIdx.x;
    __shared__ float As[BK][BM];
    __shared__ float Bs[BK][BN];

    const int brow = blockIdx.y * BM;
    const int bcol = blockIdx.x * BN;

    constexpr int TCOLS = BN / TN;
    const int tr = tid / TCOLS;
    const int tc = tid % TCOLS;

    // A loader: BM x BK, one float4 along k per thread
    constexpr int A_K4 = BK / 4;
    const int arow = tid / A_K4;
    const int ak4  = (tid % A_K4) * 4;
    // B loader (non-trans): BK x BN, one float4 along n per thread
    constexpr int B_N4 = BN / 4;
    const int bkrow = tid / B_N4;
    const int bn4   = (tid % B_N4) * 4;
    // B loader (trans): BN x BK, one float4 along k per thread
    const int btn  = tid / A_K4;
    const int btk4 = (tid % A_K4) * 4;

    float acc[TM][TN];
#pragma unroll
    for (int i = 0; i < TM; i++)
#pragma unroll
        for (int j = 0; j < TN; j++) acc[i][j] = 0.f;

    for (int k0 = 0; k0 < K; k0 += BK) {
        float4 av = *reinterpret_cast<const float4*>(
            &Ag[(long)(brow + arow) * lda + k0 + ak4]);
        As[ak4 + 0][arow] = av.x;
        As[ak4 + 1][arow] = av.y;
        As[ak4 + 2][arow] = av.z;
        As[ak4 + 3][arow] = av.w;
        if (!TB) {
            float4 bv = *reinterpret_cast<const float4*>(
                &Bg[(long)(k0 + bkrow) * ldb + bcol + bn4]);
            *reinterpret_cast<float4*>(&Bs[bkrow][bn4]) = bv;
        } else {
            float4 bv = *reinterpret_cast<const float4*>(
                &Bg[(long)(bcol + btn) * ldb + k0 + btk4]);
            Bs[btk4 + 0][btn] = bv.x;
            Bs[btk4 + 1][btn] = bv.y;
            Bs[btk4 + 2][btn] = bv.z;
            Bs[btk4 + 3][btn] = bv.w;
        }
        __syncthreads();
#pragma unroll
        for (int kk = 0; kk < BK; kk++) {
            float ra[TM], rb[TN];
#pragma unroll
            for (int i = 0; i < TM; i++) ra[i] = As[kk][tr * TM + i];
#pragma unroll
            for (int j = 0; j < TN; j++) rb[j] = Bs[kk][tc * TN + j];
#pragma unroll
            for (int i = 0; i < TM; i++)
#pragma unroll
                for (int j = 0; j < TN; j++)
                    acc[i][j] = fmaf(ra[i], rb[j], acc[i][j]);
        }
        __syncthreads();
    }

#pragma unroll
    for (int i = 0; i < TM; i++) {
        long rowBase = (long)(brow + tr * TM + i) * ldc + bcol + tc * TN;
#pragma unroll
        for (int j = 0; j < TN; j++) {
            float v = acc[i][j] * alpha;
            if (bias) v += bias[bcol + tc * TN + j];
            if (relu) v = fmaxf(v, 0.f);
            Cg[rowBase + j] = v;
        }
    }
}

// ---------------------------------------------------------------------------
// Final copy x -> d_out (float4)
// ---------------------------------------------------------------------------
__global__ void copy4_kernel(const float4* __restrict__ src,
                             float4* __restrict__ dst, int n4) {
    int i = blockIdx.x * blockDim.x + threadIdx.x;
    if (i < n4) dst[i] = src[i];
}

// ---------------------------------------------------------------------------
// Host launcher
// ---------------------------------------------------------------------------
extern "C" void kernel_launch(void* const* d_in, const int* in_sizes, int n_in,
                              void* d_out, int out_size) {
    const float* enc   = (const float*)d_in[0];
    const float* val_w = (const float*)d_in[1];
    const float* val_b = (const float*)d_in[2];
    const float* pos   = (const float*)d_in[3];
    const float* Wq    = (const float*)d_in[4];
    const float* bq    = (const float*)d_in[5];
    const float* Wk    = (const float*)d_in[6];
    const float* bk    = (const float*)d_in[7];
    const float* Wv    = (const float*)d_in[8];
    const float* bv    = (const float*)d_in[9];
    const float* Wo    = (const float*)d_in[10];
    const float* bo    = (const float*)d_in[11];
    const float* ln1_g = (const float*)d_in[12];
    const float* ln1_b = (const float*)d_in[13];
    const float* c1_w  = (const float*)d_in[14];
    const float* c1_b  = (const float*)d_in[15];
    const float* c2_w  = (const float*)d_in[16];
    const float* c2_b  = (const float*)d_in[17];
    const float* ln2_g = (const float*)d_in[18];
    const float* ln2_b = (const float*)d_in[19];

    float *x, *q, *k, *v, *ctx, *tmp, *ffn;
    cudaGetSymbolAddress((void**)&x,   g_x);
    cudaGetSymbolAddress((void**)&q,   g_q);
    cudaGetSymbolAddress((void**)&k,   g_k);
    cudaGetSymbolAddress((void**)&v,   g_v);
    cudaGetSymbolAddress((void**)&ctx, g_ctx);
    cudaGetSymbolAddress((void**)&tmp, g_tmp);
    cudaGetSymbolAddress((void**)&ffn, g_ffn);

    float* out = (float*)d_out;
    float* attn_all = out + (size_t)B_ * S_ * D_;   // x first, then attns

    // Embedding
    embed_kernel<<<(T_ * D_ + 255) / 256, 256>>>(enc, val_w, val_b, pos, x);

    const long SD  = (long)S_ * D_;
    const long SS  = (long)S_ * S_;
    const long HSS = (long)H_ * SS;

    for (int l = 0; l < L_; l++) {
        const float* Wq_l = Wq + (long)l * D_ * D_;
        const float* Wk_l = Wk + (long)l * D_ * D_;
        const float* Wv_l = Wv + (long)l * D_ * D_;
        const float* Wo_l = Wo + (long)l * D_ * D_;
        const float* c1w_l = c1_w + (long)l * D_ * F_;
        const float* c2w_l = c2_w + (long)l * F_ * D_;
        float* attnL = attn_all + (long)l * B_ * HSS;

        dim3 gProj(D_ / 128, T_ / 128, 1);   // (4,32,1)
        // Q, K, V projections: [4096,512] @ [512,512] + bias
        gemm_kernel<128, 128, 8, 8, 8, false><<<gProj, 256>>>(
            x, Wq_l, q, bq + l * D_, T_, D_, D_, D_, D_, D_,
            0, 0, 0, 0, 0, 0, 1, 1.f, 0);
        gemm_kernel<128, 128, 8, 8, 8, false><<<gProj, 256>>>(
            x, Wk_l, k, bk + l * D_, T_, D_, D_, D_, D_, D_,
            0, 0, 0, 0, 0, 0, 1, 1.f, 0);
        gemm_kernel<128, 128, 8, 8, 8, false><<<gProj, 256>>>(
            x, Wv_l, v, bv + l * D_, T_, D_, D_, D_, D_, D_,
            0, 0, 0, 0, 0, 0, 1, 1.f, 0);

        // scores = Q_bh @ K_bh^T * scale  -> written straight into d_out slot
        dim3 gScore(S_ / 128, S_ / 128, B_ * H_);   // (4,4,64)
        gemm_kernel<128, 128, 8, 8, 8, true><<<gScore, 256>>>(
            q, k, attnL, nullptr, S_, S_, DK_, D_, D_, S_,
            SD, DK_, SD, DK_, HSS, SS, H_, SCALE_, 0);

        // softmax rows in place
        softmax512_kernel<<<B_ * H_ * S_, 256>>>(attnL);

        // ctx = attn @ V_bh  -> [B,S,D] layout via head offsets
        dim3 gCtx(DK_ / 64, S_ / 64, B_ * H_);      // (1,8,64)
        gemm_kernel<64, 64, 16, 4, 4, false><<<gCtx, 256>>>(
            attnL, v, ctx, nullptr, S_, DK_, S_, S_, D_, D_,
            HSS, SS, SD, DK_, SD, DK_, H_, 1.f, 0);

        // out proj + residual LN1
        gemm_kernel<128, 128, 8, 8, 8, false><<<gProj, 256>>>(
            ctx, Wo_l, tmp, bo + l * D_, T_, D_, D_, D_, D_, D_,
            0, 0, 0, 0, 0, 0, 1, 1.f, 0);
        ln_residual_kernel<<<T_, 256>>>(tmp, x, ln1_g + l * D_, ln1_b + l * D_);

        // FFN: relu(x @ c1 + b1) @ c2 + b2, residual LN2
        dim3 gF1(F_ / 128, T_ / 128, 1);            // (16,32,1)
        gemm_kernel<128, 128, 8, 8, 8, false><<<gF1, 256>>>(
            x, c1w_l, ffn, c1_b + l * F_, T_, F_, D_, D_, F_, F_,
            0, 0, 0, 0, 0, 0, 1, 1.f, 1);
        gemm_kernel<128, 128, 8, 8, 8, false><<<gProj, 256>>>(
            ffn, c2w_l, tmp, c2_b + l * D_, T_, D_, F_, F_, D_, D_,
            0, 0, 0, 0, 0, 0, 1, 1.f, 0);
        ln_residual_kernel<<<T_, 256>>>(tmp, x, ln2_g + l * D_, ln2_b + l * D_);
    }

    // final hidden states -> front of d_out
    int n4 = T_ * D_ / 4;
    copy4_kernel<<<(n4 + 255) / 256, 256>>>((const float4*)x, (float4*)out, n4);
}

// round 2
// speedup vs baseline: 2.9077x; 2.9077x over previous
#include <cuda_runtime.h>
#include <math.h>
#include <stdint.h>

// ---------------------------------------------------------------------------
// Problem constants
// ---------------------------------------------------------------------------
namespace {
constexpr int B_ = 8, S_ = 512, C_ = 12, D_ = 512, H_ = 8, F_ = 2048, L_ = 4;
constexpr int DK_ = D_ / H_;          // 64
constexpr int T_  = B_ * S_;          // 4096 tokens
constexpr float EPS_ = 1e-5f;
constexpr float SCALE_ = 0.125f;      // 1/sqrt(64)
}

// ---------------------------------------------------------------------------
// Scratch (static device globals -- no allocations allowed)
// ---------------------------------------------------------------------------
__device__ float g_x  [T_ * D_];
__device__ float g_q  [T_ * D_];
__device__ float g_k  [T_ * D_];
__device__ float g_v  [T_ * D_];
__device__ float g_ctx[T_ * D_];
__device__ float g_tmp[T_ * D_];
__device__ float g_ffn[T_ * F_];

// ---------------------------------------------------------------------------
// Embedding: x = enc @ val_w + val_b + pos    (K = 12, trivially small)
// ---------------------------------------------------------------------------
__global__ void embed_kernel(const float* __restrict__ enc,
                             const float* __restrict__ vw,
                             const float* __restrict__ vb,
                             const float* __restrict__ pos,
                             float* __restrict__ x) {
    int idx = blockIdx.x * blockDim.x + threadIdx.x;
    if (idx >= T_ * D_) return;
    int t = idx >> 9;
    int d = idx & (D_ - 1);
    int s = t & (S_ - 1);
    float acc = vb[d] + pos[s * D_ + d];
    const float* e = enc + t * C_;
#pragma unroll
    for (int c = 0; c < C_; c++) acc = fmaf(e[c], vw[c * D_ + d], acc);
    x[idx] = acc;
}

// ---------------------------------------------------------------------------
// Reductions (block = 256)
// ---------------------------------------------------------------------------
__device__ __forceinline__ float warpReduceSum(float v) {
#pragma unroll
    for (int o = 16; o > 0; o >>= 1) v += __shfl_xor_sync(0xffffffffu, v, o);
    return v;
}
__device__ __forceinline__ float warpReduceMax(float v) {
#pragma unroll
    for (int o = 16; o > 0; o >>= 1) v = fmaxf(v, __shfl_xor_sync(0xffffffffu, v, o));
    return v;
}
__device__ __forceinline__ float blockReduceSum(float v, float* sh) {
    int lane = threadIdx.x & 31, wid = threadIdx.x >> 5;
    v = warpReduceSum(v);
    __syncthreads();
    if (lane == 0) sh[wid] = v;
    __syncthreads();
    if (wid == 0) {
        float t = (lane < 8) ? sh[lane] : 0.f;
        t = warpReduceSum(t);
        if (lane == 0) sh[0] = t;
    }
    __syncthreads();
    return sh[0];
}
__device__ __forceinline__ float blockReduceMax(float v, float* sh) {
    int lane = threadIdx.x & 31, wid = threadIdx.x >> 5;
    v = warpReduceMax(v);
    __syncthreads();
    if (lane == 0) sh[wid] = v;
    __syncthreads();
    if (wid == 0) {
        float t = (lane < 8) ? sh[lane] : -INFINITY;
        t = warpReduceMax(t);
        if (lane == 0) sh[0] = t;
    }
    __syncthreads();
    return sh[0];
}

// ---------------------------------------------------------------------------
// Softmax over rows of length 512, in place. grid = numRows, block = 256.
// ---------------------------------------------------------------------------
__global__ void softmax512_kernel(float* __restrict__ data) {
    __shared__ float sh[32];
    float* p = data + (size_t)blockIdx.x * 512;
    int t = threadIdx.x;
    float v0 = p[t], v1 = p[t + 256];
    float m = blockReduceMax(fmaxf(v0, v1), sh);
    float e0 = expf(v0 - m), e1 = expf(v1 - m);
    float s = blockReduceSum(e0 + e1, sh);
    float inv = 1.f / s;
    p[t]       = e0 * inv;
    p[t + 256] = e1 * inv;
}

// ---------------------------------------------------------------------------
// Residual add + LayerNorm: x = LN(y + x) * g + b. Row length 512. block=256.
// ---------------------------------------------------------------------------
__global__ void ln_residual_kernel(const float* __restrict__ y,
                                   float* __restrict__ x,
                                   const float* __restrict__ g,
                                   const float* __restrict__ b) {
    __shared__ float sh[32];
    size_t base = (size_t)blockIdx.x * 512;
    int t = threadIdx.x;
    float s0 = y[base + t]       + x[base + t];
    float s1 = y[base + t + 256] + x[base + t + 256];
    float mean = blockReduceSum(s0 + s1, sh) * (1.f / 512.f);
    float d0 = s0 - mean, d1 = s1 - mean;
    float var = blockReduceSum(d0 * d0 + d1 * d1, sh) * (1.f / 512.f);
    float rs = rsqrtf(var + EPS_);
    x[base + t]       = d0 * rs * g[t]       + b[t];
    x[base + t + 256] = d1 * rs * g[t + 256] + b[t + 256];
}

// ---------------------------------------------------------------------------
// TF32 tensor-core batched-strided GEMM.
//   C = alpha * A @ op(B) + bias (+relu)
// A: [M,K] row-major (lda). TB=false: B [K,N] row-major; TB=true: B [N,K].
// Block tile 128x64, BK=32, 256 threads (8 warps of 32x32), double-buffered
// swizzled shared, fp32->tf32 cvt.rna on the shared-store path.
// ---------------------------------------------------------------------------
__device__ __forceinline__ uint32_t f2tf(float f) {
    uint32_t r;
    asm("cvt.rna.tf32.f32 %0, %1;" : "=r"(r) : "f"(f));
    return r;
}

template <bool TB>
__global__ __launch_bounds__(256) void mma_gemm_kernel(
    const float* __restrict__ Ag, const float* __restrict__ Bg,
    float* __restrict__ Cg, const float* __restrict__ bias,
    int M, int N, int K, int lda, int ldb, int ldc,
    long aO, long aI, long bO, long bI, long cO, long cI, int bH,
    float alpha, int relu) {
    constexpr int BM = 128, BN = 64, BK = 32;

    __shared__ uint32_t sA[2][BM * BK];   // 32 KB
    __shared__ uint32_t sB[2][BN * BK];   // 16 KB

    const int z = blockIdx.z;
    Ag += (long)(z / bH) * aO + (long)(z % bH) * aI;
    Bg += (long)(z / bH) * bO + (long)(z % bH) * bI;
    Cg += (long)(z / bH) * cO + (long)(z % bH) * cI;

    const int tid  = threadIdx.x;
    const int lane = tid & 31;
    const int warp = tid >> 5;
    const int brow = blockIdx.y * BM;
    const int bcol = blockIdx.x * BN;
    const int warpM = (warp >> 1) * 32;   // 4 warps along M
    const int warpN = (warp & 1) * 32;    // 2 warps along N

    const uint32_t aBase = (uint32_t)__cvta_generic_to_shared(&sA[0][0]);
    const uint32_t bBase = (uint32_t)__cvta_generic_to_shared(&sB[0][0]);

    float acc[2][4][4];
#pragma unroll
    for (int i = 0; i < 2; i++)
#pragma unroll
        for (int j = 0; j < 4; j++)
#pragma unroll
            for (int c = 0; c < 4; c++) acc[i][j][c] = 0.f;

    // per-thread loader coordinates
    const int aRow = tid >> 3;            // 0..31 (covers 128 rows in 4 steps)
    const int aChunk = tid & 7;           // 16B chunk within a 32-float row
    const int bRowT = tid >> 3;           // TB path
    const int bChunkT = tid & 7;
    const int bKrow = tid >> 4;           // non-TB path: k row 0..15 (2 steps)
    const int bN0 = (tid & 15) * 4;       // 4 consecutive n

    float4 pa[4];
    float4 pb[2];

    auto ldg = [&](int t) {
#pragma unroll
        for (int i = 0; i < 4; i++) {
            int row = aRow + i * 32;
            pa[i] = *reinterpret_cast<const float4*>(
                &Ag[(long)(brow + row) * lda + t * BK + aChunk * 4]);
        }
        if (TB) {
#pragma unroll
            for (int i = 0; i < 2; i++) {
                int row = bRowT + i * 32;
                pb[i] = *reinterpret_cast<const float4*>(
                    &Bg[(long)(bcol + row) * ldb + t * BK + bChunkT * 4]);
            }
        } else {
#pragma unroll
            for (int i = 0; i < 2; i++) {
                int kr = bKrow + i * 16;
                pb[i] = *reinterpret_cast<const float4*>(
                    &Bg[(long)(t * BK + kr) * ldb + bcol + bN0]);
            }
        }
    };

    auto sts = [&](int buf) {
#pragma unroll
        for (int i = 0; i < 4; i++) {
            int row = aRow + i * 32;
            uint32_t off = row * BK + (((uint32_t)aChunk ^ (row & 7)) << 2);
            uint4 v = make_uint4(f2tf(pa[i].x), f2tf(pa[i].y),
                                 f2tf(pa[i].z), f2tf(pa[i].w));
            *reinterpret_cast<uint4*>(&sA[buf][off]) = v;
        }
        if (TB) {
#pragma unroll
            for (int i = 0; i < 2; i++) {
                int row = bRowT + i * 32;
                uint32_t off = row * BK + (((uint32_t)bChunkT ^ (row & 7)) << 2);
                uint4 v = make_uint4(f2tf(pb[i].x), f2tf(pb[i].y),
                                     f2tf(pb[i].z), f2tf(pb[i].w));
                *reinterpret_cast<uint4*>(&sB[buf][off]) = v;
            }
        } else {
#pragma unroll
            for (int i = 0; i < 2; i++) {
                int kr = bKrow + i * 16;
                float e[4] = {pb[i].x, pb[i].y, pb[i].z, pb[i].w};
#pragma unroll
                for (int j = 0; j < 4; j++) {
                    int n = bN0 + j;
                    sB[buf][n * BK + ((((uint32_t)(kr >> 2)) ^ (n & 7)) << 2) +
                            (kr & 3)] = f2tf(e[j]);
                }
            }
        }
    };

    auto compute = [&](int buf) {
        const uint32_t aB = aBase + (uint32_t)buf * BM * BK * 4;
        const uint32_t bB = bBase + (uint32_t)buf * BN * BK * 4;
#pragma unroll
        for (int ks = 0; ks < 4; ks++) {
            uint32_t af[2][4];
            uint32_t bf[4][2];
#pragma unroll
            for (int i = 0; i < 2; i++) {
                int sub = lane >> 3, r = lane & 7;
                int row = warpM + i * 16 + (sub & 1) * 8 + r;
                int chunk = ks * 2 + (sub >> 1);
                uint32_t off = row * BK + (((uint32_t)chunk ^ (row & 7)) << 2);
                uint32_t addr = aB + off * 4;
                asm volatile(
                    "ldmatrix.sync.aligned.m8n8.x4.shared.b16 {%0,%1,%2,%3}, [%4];"
                    : "=r"(af[i][0]), "=r"(af[i][1]), "=r"(af[i][2]), "=r"(af[i][3])
                    : "r"(addr));
            }
#pragma unroll
            for (int j = 0; j < 4; j++) {
                int l = lane & 15;
                int sub = l >> 3, r = l & 7;
                int row = warpN + j * 8 + r;
                int chunk = ks * 2 + sub;
                uint32_t off = row * BK + (((uint32_t)chunk ^ (row & 7)) << 2);
                uint32_t addr = bB + off * 4;
                asm volatile(
                    "ldmatrix.sync.aligned.m8n8.x2.shared.b16 {%0,%1}, [%2];"
                    : "=r"(bf[j][0]), "=r"(bf[j][1])
                    : "r"(addr));
            }
#pragma unroll
            for (int i = 0; i < 2; i++)
#pragma unroll
                for (int j = 0; j < 4; j++) {
                    asm volatile(
                        "mma.sync.aligned.m16n8k8.row.col.f32.tf32.tf32.f32 "
                        "{%0,%1,%2,%3}, {%4,%5,%6,%7}, {%8,%9}, {%0,%1,%2,%3};"
                        : "+f"(acc[i][j][0]), "+f"(acc[i][j][1]),
                          "+f"(acc[i][j][2]), "+f"(acc[i][j][3])
                        : "r"(af[i][0]), "r"(af[i][1]), "r"(af[i][2]),
                          "r"(af[i][3]), "r"(bf[j][0]), "r"(bf[j][1]));
                }
        }
    };

    const int nk = K / BK;
    ldg(0);
    sts(0);
    __syncthreads();
#pragma unroll 1
    for (int t = 0; t < nk; t++) {
        if (t + 1 < nk) ldg(t + 1);
        compute(t & 1);
        if (t + 1 < nk) sts((t + 1) & 1);
        __syncthreads();
    }

    // epilogue
    const int g  = lane >> 2;
    const int tg = lane & 3;
#pragma unroll
    for (int i = 0; i < 2; i++) {
#pragma unroll
        for (int j = 0; j < 4; j++) {
            int colL = warpN + j * 8 + tg * 2;
            int col  = bcol + colL;
            float b0 = 0.f, b1 = 0.f;
            if (bias) { b0 = bias[col]; b1 = bias[col + 1]; }
            int row0 = brow + warpM + i * 16 + g;
            float v0 = acc[i][j][0] * alpha + b0;
            float v1 = acc[i][j][1] * alpha + b1;
            float v2 = acc[i][j][2] * alpha + b0;
            float v3 = acc[i][j][3] * alpha + b1;
            if (relu) {
                v0 = fmaxf(v0, 0.f); v1 = fmaxf(v1, 0.f);
                v2 = fmaxf(v2, 0.f); v3 = fmaxf(v3, 0.f);
            }
            *reinterpret_cast<float2*>(&Cg[(long)row0 * ldc + col]) =
                make_float2(v0, v1);
            *reinterpret_cast<float2*>(&Cg[(long)(row0 + 8) * ldc + col]) =
                make_float2(v2, v3);
        }
    }
}

// ---------------------------------------------------------------------------
// Final copy x -> d_out (float4)
// ---------------------------------------------------------------------------
__global__ void copy4_kernel(const float4* __restrict__ src,
                             float4* __restrict__ dst, int n4) {
    int i = blockIdx.x * blockDim.x + threadIdx.x;
    if (i < n4) dst[i] = src[i];
}

// ---------------------------------------------------------------------------
// Host launcher
// ---------------------------------------------------------------------------
extern "C" void kernel_launch(void* const* d_in, const int* in_sizes, int n_in,
                              void* d_out, int out_size) {
    const float* enc   = (const float*)d_in[0];
    const float* val_w = (const float*)d_in[1];
    const float* val_b = (const float*)d_in[2];
    const float* pos   = (const float*)d_in[3];
    const float* Wq    = (const float*)d_in[4];
    const float* bq    = (const float*)d_in[5];
    const float* Wk    = (const float*)d_in[6];
    const float* bk    = (const float*)d_in[7];
    const float* Wv    = (const float*)d_in[8];
    const float* bv    = (const float*)d_in[9];
    const float* Wo    = (const float*)d_in[10];
    const float* bo    = (const float*)d_in[11];
    const float* ln1_g = (const float*)d_in[12];
    const float* ln1_b = (const float*)d_in[13];
    const float* c1_w  = (const float*)d_in[14];
    const float* c1_b  = (const float*)d_in[15];
    const float* c2_w  = (const float*)d_in[16];
    const float* c2_b  = (const float*)d_in[17];
    const float* ln2_g = (const float*)d_in[18];
    const float* ln2_b = (const float*)d_in[19];

    float *x, *q, *k, *v, *ctx, *tmp, *ffn;
    cudaGetSymbolAddress((void**)&x,   g_x);
    cudaGetSymbolAddress((void**)&q,   g_q);
    cudaGetSymbolAddress((void**)&k,   g_k);
    cudaGetSymbolAddress((void**)&v,   g_v);
    cudaGetSymbolAddress((void**)&ctx, g_ctx);
    cudaGetSymbolAddress((void**)&tmp, g_tmp);
    cudaGetSymbolAddress((void**)&ffn, g_ffn);

    float* out = (float*)d_out;
    float* attn_all = out + (size_t)B_ * S_ * D_;   // x first, then attns

    embed_kernel<<<(T_ * D_ + 255) / 256, 256>>>(enc, val_w, val_b, pos, x);

    const long SD  = (long)S_ * D_;
    const long SS  = (long)S_ * S_;
    const long HSS = (long)H_ * SS;

    for (int l = 0; l < L_; l++) {
        const float* Wq_l = Wq + (long)l * D_ * D_;
        const float* Wk_l = Wk + (long)l * D_ * D_;
        const float* Wv_l = Wv + (long)l * D_ * D_;
        const float* Wo_l = Wo + (long)l * D_ * D_;
        const float* c1w_l = c1_w + (long)l * D_ * F_;
        const float* c2w_l = c2_w + (long)l * F_ * D_;
        float* attnL = attn_all + (long)l * B_ * HSS;

        dim3 gProj(D_ / 64, T_ / 128, 1);   // (8,32,1)
        mma_gemm_kernel<false><<<gProj, 256>>>(
            x, Wq_l, q, bq + l * D_, T_, D_, D_, D_, D_, D_,
            0, 0, 0, 0, 0, 0, 1, 1.f, 0);
        mma_gemm_kernel<false><<<gProj, 256>>>(
            x, Wk_l, k, bk + l * D_, T_, D_, D_, D_, D_, D_,
            0, 0, 0, 0, 0, 0, 1, 1.f, 0);
        mma_gemm_kernel<false><<<gProj, 256>>>(
            x, Wv_l, v, bv + l * D_, T_, D_, D_, D_, D_, D_,
            0, 0, 0, 0, 0, 0, 1, 1.f, 0);

        // scores = Q_bh @ K_bh^T * scale  (straight into d_out slot)
        dim3 gScore(S_ / 64, S_ / 128, B_ * H_);   // (8,4,64)
        mma_gemm_kernel<true><<<gScore, 256>>>(
            q, k, attnL, nullptr, S_, S_, DK_, D_, D_, S_,
            SD, DK_, SD, DK_, HSS, SS, H_, SCALE_, 0);

        softmax512_kernel<<<B_ * H_ * S_, 256>>>(attnL);

        // ctx = attn @ V_bh
        dim3 gCtx(DK_ / 64, S_ / 128, B_ * H_);    // (1,4,64)
        mma_gemm_kernel<false><<<gCtx, 256>>>(
            attnL, v, ctx, nullptr, S_, DK_, S_, S_, D_, D_,
            HSS, SS, SD, DK_, SD, DK_, H_, 1.f, 0);

        // out proj + residual LN1
        mma_gemm_kernel<false><<<gProj, 256>>>(
            ctx, Wo_l, tmp, bo + l * D_, T_, D_, D_, D_, D_, D_,
            0, 0, 0, 0, 0, 0, 1, 1.f, 0);
        ln_residual_kernel<<<T_, 256>>>(tmp, x, ln1_g + l * D_, ln1_b + l * D_);

        // FFN
        dim3 gF1(F_ / 64, T_ / 128, 1);            // (32,32,1)
        mma_gemm_kernel<false><<<gF1, 256>>>(
            x, c1w_l, ffn, c1_b + l * F_, T_, F_, D_, D_, F_, F_,
            0, 0, 0, 0, 0, 0, 1, 1.f, 1);
        mma_gemm_kernel<false><<<gProj, 256>>>(
            ffn, c2w_l, tmp, c2_b + l * D_, T_, D_, F_, F_, D_, D_,
            0, 0, 0, 0, 0, 0, 1, 1.f, 0);
        ln_residual_kernel<<<T_, 256>>>(tmp, x, ln2_g + l * D_, ln2_b + l * D_);
    }

    int n4 = T_ * D_ / 4;
    copy4_kernel<<<(n4 + 255) / 256, 256>>>((const float4*)x, (float4*)out, n4);
}

// round 3
// speedup vs baseline: 3.5314x; 1.2145x over previous
#include <cuda_runtime.h>
#include <math.h>
#include <stdint.h>

// ---------------------------------------------------------------------------
// Problem constants
// ---------------------------------------------------------------------------
namespace {
constexpr int B_ = 8, S_ = 512, C_ = 12, D_ = 512, H_ = 8, F_ = 2048, L_ = 4;
constexpr int DK_ = D_ / H_;          // 64
constexpr int T_  = B_ * S_;          // 4096 tokens
constexpr float EPS_ = 1e-5f;
constexpr float SCALE_ = 0.125f;      // 1/sqrt(64)
}

// ---------------------------------------------------------------------------
// Scratch (static device globals -- no allocations allowed)
// ---------------------------------------------------------------------------
__device__ float g_x  [T_ * D_];
__device__ float g_q  [T_ * D_];
__device__ float g_k  [T_ * D_];
__device__ float g_v  [T_ * D_];
__device__ float g_ctx[T_ * D_];
__device__ float g_tmp[T_ * D_];
__device__ float g_ffn[T_ * F_];
// transposed weights: [16 x 512x512 attn] [4 x 2048x512 c1T] [4 x 512x2048 c2T]
__device__ float g_wT [12582912];

namespace {
constexpr long WT_ATTN = 0;                 // (l*4+m)*262144
constexpr long WT_C1   = 4194304;           // + l*1048576
constexpr long WT_C2   = 8388608;           // + l*1048576
}

// ---------------------------------------------------------------------------
// Embedding: x = enc @ val_w + val_b + pos
// ---------------------------------------------------------------------------
__global__ void embed_kernel(const float* __restrict__ enc,
                             const float* __restrict__ vw,
                             const float* __restrict__ vb,
                             const float* __restrict__ pos,
                             float* __restrict__ x) {
    int idx = blockIdx.x * blockDim.x + threadIdx.x;
    if (idx >= T_ * D_) return;
    int t = idx >> 9;
    int d = idx & (D_ - 1);
    int s = t & (S_ - 1);
    float acc = vb[d] + pos[s * D_ + d];
    const float* e = enc + t * C_;
#pragma unroll
    for (int c = 0; c < C_; c++) acc = fmaf(e[c], vw[c * D_ + d], acc);
    x[idx] = acc;
}

// ---------------------------------------------------------------------------
// Transpose helpers: src [R,C] row-major -> dst [C,R] row-major.
// block (32,8), grid (C/32, R/32, batch)
// ---------------------------------------------------------------------------
__device__ __forceinline__ void transpose_tile(const float* __restrict__ src,
                                               float* __restrict__ dst,
                                               int R, int C) {
    __shared__ float sh[32][33];
    int x  = blockIdx.x * 32 + threadIdx.x;
    int y0 = blockIdx.y * 32 + threadIdx.y;
#pragma unroll
    for (int i = 0; i < 4; i++)
        sh[threadIdx.y + i * 8][threadIdx.x] = src[(long)(y0 + i * 8) * C + x];
    __syncthreads();
    int xo  = blockIdx.y * 32 + threadIdx.x;
    int yo0 = blockIdx.x * 32 + threadIdx.y;
#pragma unroll
    for (int i = 0; i < 4; i++)
        dst[(long)(yo0 + i * 8) * R + xo] = sh[threadIdx.x][threadIdx.y + i * 8];
}

__global__ void transpose_attn_kernel(const float* __restrict__ Wq,
                                      const float* __restrict__ Wk,
                                      const float* __restrict__ Wv,
                                      const float* __restrict__ Wo,
                                      float* __restrict__ dst) {
    int z = blockIdx.z, l = z >> 2, m = z & 3;
    const float* src = (m == 0) ? Wq : (m == 1) ? Wk : (m == 2) ? Wv : Wo;
    src += (long)l * D_ * D_;
    transpose_tile(src, dst + (long)z * D_ * D_, D_, D_);
}

__global__ void transpose_c1_kernel(const float* __restrict__ c1,
                                    float* __restrict__ dst) {
    int l = blockIdx.z;
    transpose_tile(c1 + (long)l * D_ * F_, dst + (long)l * D_ * F_, D_, F_);
}

__global__ void transpose_c2_kernel(const float* __restrict__ c2,
                                    float* __restrict__ dst) {
    int l = blockIdx.z;
    transpose_tile(c2 + (long)l * F_ * D_, dst + (long)l * F_ * D_, F_, D_);
}

// ---------------------------------------------------------------------------
// Reductions (block = 256)
// ---------------------------------------------------------------------------
__device__ __forceinline__ float warpReduceSum(float v) {
#pragma unroll
    for (int o = 16; o > 0; o >>= 1) v += __shfl_xor_sync(0xffffffffu, v, o);
    return v;
}
__device__ __forceinline__ float warpReduceMax(float v) {
#pragma unroll
    for (int o = 16; o > 0; o >>= 1) v = fmaxf(v, __shfl_xor_sync(0xffffffffu, v, o));
    return v;
}
__device__ __forceinline__ float blockReduceSum(float v, float* sh) {
    int lane = threadIdx.x & 31, wid = threadIdx.x >> 5;
    v = warpReduceSum(v);
    __syncthreads();
    if (lane == 0) sh[wid] = v;
    __syncthreads();
    if (wid == 0) {
        float t = (lane < 8) ? sh[lane] : 0.f;
        t = warpReduceSum(t);
        if (lane == 0) sh[0] = t;
    }
    __syncthreads();
    return sh[0];
}
__device__ __forceinline__ float blockReduceMax(float v, float* sh) {
    int lane = threadIdx.x & 31, wid = threadIdx.x >> 5;
    v = warpReduceMax(v);
    __syncthreads();
    if (lane == 0) sh[wid] = v;
    __syncthreads();
    if (wid == 0) {
        float t = (lane < 8) ? sh[lane] : -INFINITY;
        t = warpReduceMax(t);
        if (lane == 0) sh[0] = t;
    }
    __syncthreads();
    return sh[0];
}

// ---------------------------------------------------------------------------
// Softmax over rows of length 512, in place. grid = numRows, block = 256.
// ---------------------------------------------------------------------------
__global__ void softmax512_kernel(float* __restrict__ data) {
    __shared__ float sh[32];
    float* p = data + (size_t)blockIdx.x * 512;
    int t = threadIdx.x;
    float v0 = p[t], v1 = p[t + 256];
    float m = blockReduceMax(fmaxf(v0, v1), sh);
    float e0 = expf(v0 - m), e1 = expf(v1 - m);
    float s = blockReduceSum(e0 + e1, sh);
    float inv = 1.f / s;
    p[t]       = e0 * inv;
    p[t + 256] = e1 * inv;
}

// ---------------------------------------------------------------------------
// Residual add + LayerNorm: x = LN(y + x) * g + b. block=256.
// ---------------------------------------------------------------------------
__global__ void ln_residual_kernel(const float* __restrict__ y,
                                   float* __restrict__ x,
                                   const float* __restrict__ g,
                                   const float* __restrict__ b) {
    __shared__ float sh[32];
    size_t base = (size_t)blockIdx.x * 512;
    int t = threadIdx.x;
    float s0 = y[base + t]       + x[base + t];
    float s1 = y[base + t + 256] + x[base + t + 256];
    float mean = blockReduceSum(s0 + s1, sh) * (1.f / 512.f);
    float d0 = s0 - mean, d1 = s1 - mean;
    float var = blockReduceSum(d0 * d0 + d1 * d1, sh) * (1.f / 512.f);
    float rs = rsqrtf(var + EPS_);
    x[base + t]       = d0 * rs * g[t]       + b[t];
    x[base + t + 256] = d1 * rs * g[t + 256] + b[t + 256];
}

// ---------------------------------------------------------------------------
// TF32 tensor-core batched-strided GEMM.
//   C = alpha * A @ op(B) + bias (+relu)
// A: [M,K] row-major. TB=true: B [N,K] row-major (preferred; weights are
// pre-transposed). TB=false: B [K,N] (only used for ctx @ V, BN=64).
// Block tile 128 x BN, BK=32, 256 threads, 8 warps (4x2), warp tile 32x(BN/2).
// Double-buffered swizzled shared; fp32->tf32 cvt.rna on shared-store path.
// ---------------------------------------------------------------------------
__device__ __forceinline__ uint32_t f2tf(float f) {
    uint32_t r;
    asm("cvt.rna.tf32.f32 %0, %1;" : "=r"(r) : "f"(f));
    return r;
}

template <int BN, bool TB>
__global__ __launch_bounds__(256, 2) void mma_gemm_kernel(
    const float* __restrict__ Ag, const float* __restrict__ Bg,
    float* __restrict__ Cg, const float* __restrict__ bias,
    int K, int lda, int ldb, int ldc,
    long aO, long aI, long bO, long bI, long cO, long cI, int bH,
    float alpha, int relu) {
    constexpr int BM = 128, BK = 32;
    constexpr int JT = (BN / 2) / 8;          // n-tiles per warp (8 or 4)
    constexpr int ASZ = BM * BK;              // u32 per A stage
    constexpr int BSZ = BN * BK;

    extern __shared__ uint32_t smem[];
    uint32_t* sA = smem;                      // [2][ASZ]
    uint32_t* sB = smem + 2 * ASZ;            // [2][BSZ]

    const int z = blockIdx.z;
    Ag += (long)(z / bH) * aO + (long)(z % bH) * aI;
    Bg += (long)(z / bH) * bO + (long)(z % bH) * bI;
    Cg += (long)(z / bH) * cO + (long)(z % bH) * cI;

    const int tid  = threadIdx.x;
    const int lane = tid & 31;
    const int warp = tid >> 5;
    const int brow = blockIdx.y * BM;
    const int bcol = blockIdx.x * BN;
    const int warpM = (warp >> 1) * 32;       // 4 warps along M
    const int warpN = (warp & 1) * (BN / 2);  // 2 warps along N

    const uint32_t aBase = (uint32_t)__cvta_generic_to_shared(sA);
    const uint32_t bBase = (uint32_t)__cvta_generic_to_shared(sB);

    float acc[2][JT][4];
#pragma unroll
    for (int i = 0; i < 2; i++)
#pragma unroll
        for (int j = 0; j < JT; j++)
#pragma unroll
            for (int c = 0; c < 4; c++) acc[i][j][c] = 0.f;

    // loader coords
    const int aRow   = tid >> 3;              // 0..31
    const int aChunk = tid & 7;               // 16B chunk in 32-float row
    const int bKrow  = tid >> 4;              // non-TB: k row 0..15
    const int bN0    = (tid & 15) * 4;        // non-TB: 4 consecutive n

    float4 pa[4];
    float4 pb[(BN / 32) > 2 ? (BN / 32) : 2];

    auto ldg = [&](int t) {
#pragma unroll
        for (int i = 0; i < 4; i++) {
            int row = aRow + i * 32;
            pa[i] = *reinterpret_cast<const float4*>(
                &Ag[(long)(brow + row) * lda + t * BK + aChunk * 4]);
        }
        if (TB) {
#pragma unroll
            for (int i = 0; i < BN / 32; i++) {
                int row = aRow + i * 32;
                pb[i] = *reinterpret_cast<const float4*>(
                    &Bg[(long)(bcol + row) * ldb + t * BK + aChunk * 4]);
            }
        } else {
#pragma unroll
            for (int i = 0; i < 2; i++) {
                int kr = bKrow + i * 16;
                pb[i] = *reinterpret_cast<const float4*>(
                    &Bg[(long)(t * BK + kr) * ldb + bcol + bN0]);
            }
        }
    };

    auto sts = [&](int buf) {
#pragma unroll
        for (int i = 0; i < 4; i++) {
            int row = aRow + i * 32;
            uint32_t off = row * BK + (((uint32_t)aChunk ^ (row & 7)) << 2);
            uint4 v = make_uint4(f2tf(pa[i].x), f2tf(pa[i].y),
                                 f2tf(pa[i].z), f2tf(pa[i].w));
            *reinterpret_cast<uint4*>(&sA[buf * ASZ + off]) = v;
        }
        if (TB) {
#pragma unroll
            for (int i = 0; i < BN / 32; i++) {
                int row = aRow + i * 32;
                uint32_t off = row * BK + (((uint32_t)aChunk ^ (row & 7)) << 2);
                uint4 v = make_uint4(f2tf(pb[i].x), f2tf(pb[i].y),
                                     f2tf(pb[i].z), f2tf(pb[i].w));
                *reinterpret_cast<uint4*>(&sB[buf * BSZ + off]) = v;
            }
        } else {
#pragma unroll
            for (int i = 0; i < 2; i++) {
                int kr = bKrow + i * 16;
                float e[4] = {pb[i].x, pb[i].y, pb[i].z, pb[i].w};
#pragma unroll
                for (int j = 0; j < 4; j++) {
                    int n = bN0 + j;
                    sB[buf * BSZ + n * BK +
                       ((((uint32_t)(kr >> 2)) ^ (n & 7)) << 2) + (kr & 3)] =
                        f2tf(e[j]);
                }
            }
        }
    };

    auto compute = [&](int buf) {
        const uint32_t aB = aBase + (uint32_t)buf * ASZ * 4;
        const uint32_t bB = bBase + (uint32_t)buf * BSZ * 4;
#pragma unroll
        for (int ks = 0; ks < 4; ks++) {
            uint32_t af[2][4];
            uint32_t bf[JT][2];
#pragma unroll
            for (int i = 0; i < 2; i++) {
                int sub = lane >> 3, r = lane & 7;
                int row = warpM + i * 16 + (sub & 1) * 8 + r;
                int chunk = ks * 2 + (sub >> 1);
                uint32_t off = row * BK + (((uint32_t)chunk ^ (row & 7)) << 2);
                uint32_t addr = aB + off * 4;
                asm volatile(
                    "ldmatrix.sync.aligned.m8n8.x4.shared.b16 {%0,%1,%2,%3}, [%4];"
                    : "=r"(af[i][0]), "=r"(af[i][1]), "=r"(af[i][2]), "=r"(af[i][3])
                    : "r"(addr));
            }
#pragma unroll
            for (int jp = 0; jp < JT / 2; jp++) {
                int r = lane & 7;
                int row = warpN + jp * 16 + ((lane >> 4) & 1) * 8 + r;
                int chunk = ks * 2 + ((lane >> 3) & 1);
                uint32_t off = row * BK + (((uint32_t)chunk ^ (row & 7)) << 2);
                uint32_t addr = bB + off * 4;
                asm volatile(
                    "ldmatrix.sync.aligned.m8n8.x4.shared.b16 {%0,%1,%2,%3}, [%4];"
                    : "=r"(bf[2 * jp][0]), "=r"(bf[2 * jp][1]),
                      "=r"(bf[2 * jp + 1][0]), "=r"(bf[2 * jp + 1][1])
                    : "r"(addr));
            }
#pragma unroll
            for (int i = 0; i < 2; i++)
#pragma unroll
                for (int j = 0; j < JT; j++) {
                    asm volatile(
                        "mma.sync.aligned.m16n8k8.row.col.f32.tf32.tf32.f32 "
                        "{%0,%1,%2,%3}, {%4,%5,%6,%7}, {%8,%9}, {%0,%1,%2,%3};"
                        : "+f"(acc[i][j][0]), "+f"(acc[i][j][1]),
                          "+f"(acc[i][j][2]), "+f"(acc[i][j][3])
                        : "r"(af[i][0]), "r"(af[i][1]), "r"(af[i][2]),
                          "r"(af[i][3]), "r"(bf[j][0]), "r"(bf[j][1]));
                }
        }
    };

    const int nk = K / BK;
    ldg(0);
    sts(0);
    __syncthreads();
#pragma unroll 1
    for (int t = 0; t < nk; t++) {
        if (t + 1 < nk) ldg(t + 1);
        compute(t & 1);
        if (t + 1 < nk) sts((t + 1) & 1);
        __syncthreads();
    }

    // epilogue
    const int g  = lane >> 2;
    const int tg = lane & 3;
#pragma unroll
    for (int i = 0; i < 2; i++) {
#pragma unroll
        for (int j = 0; j < JT; j++) {
            int col = bcol + warpN + j * 8 + tg * 2;
            float b0 = 0.f, b1 = 0.f;
            if (bias) { b0 = bias[col]; b1 = bias[col + 1]; }
            int row0 = brow + warpM + i * 16 + g;
            float v0 = acc[i][j][0] * alpha + b0;
            float v1 = acc[i][j][1] * alpha + b1;
            float v2 = acc[i][j][2] * alpha + b0;
            float v3 = acc[i][j][3] * alpha + b1;
            if (relu) {
                v0 = fmaxf(v0, 0.f); v1 = fmaxf(v1, 0.f);
                v2 = fmaxf(v2, 0.f); v3 = fmaxf(v3, 0.f);
            }
            *reinterpret_cast<float2*>(&Cg[(long)row0 * ldc + col]) =
                make_float2(v0, v1);
            *reinterpret_cast<float2*>(&Cg[(long)(row0 + 8) * ldc + col]) =
                make_float2(v2, v3);
        }
    }
}

// ---------------------------------------------------------------------------
// Final copy x -> d_out (float4)
// ---------------------------------------------------------------------------
__global__ void copy4_kernel(const float4* __restrict__ src,
                             float4* __restrict__ dst, int n4) {
    int i = blockIdx.x * blockDim.x + threadIdx.x;
    if (i < n4) dst[i] = src[i];
}

// ---------------------------------------------------------------------------
// Host launcher
// ---------------------------------------------------------------------------
extern "C" void kernel_launch(void* const* d_in, const int* in_sizes, int n_in,
                              void* d_out, int out_size) {
    const float* enc   = (const float*)d_in[0];
    const float* val_w = (const float*)d_in[1];
    const float* val_b = (const float*)d_in[2];
    const float* pos   = (const float*)d_in[3];
    const float* Wq    = (const float*)d_in[4];
    const float* bq    = (const float*)d_in[5];
    const float* Wk    = (const float*)d_in[6];
    const float* bk    = (const float*)d_in[7];
    const float* Wv    = (const float*)d_in[8];
    const float* bv    = (const float*)d_in[9];
    const float* Wo    = (const float*)d_in[10];
    const float* bo    = (const float*)d_in[11];
    const float* ln1_g = (const float*)d_in[12];
    const float* ln1_b = (const float*)d_in[13];
    const float* c1_w  = (const float*)d_in[14];
    const float* c1_b  = (const float*)d_in[15];
    const float* c2_w  = (const float*)d_in[16];
    const float* c2_b  = (const float*)d_in[17];
    const float* ln2_g = (const float*)d_in[18];
    const float* ln2_b = (const float*)d_in[19];

    float *x, *q, *k, *v, *ctx, *tmp, *ffn, *wT;
    cudaGetSymbolAddress((void**)&x,   g_x);
    cudaGetSymbolAddress((void**)&q,   g_q);
    cudaGetSymbolAddress((void**)&k,   g_k);
    cudaGetSymbolAddress((void**)&v,   g_v);
    cudaGetSymbolAddress((void**)&ctx, g_ctx);
    cudaGetSymbolAddress((void**)&tmp, g_tmp);
    cudaGetSymbolAddress((void**)&ffn, g_ffn);
    cudaGetSymbolAddress((void**)&wT,  g_wT);

    // opt-in dynamic shared above 48KB for the BN=128 instantiations
    constexpr int SMEM128 = 2 * (128 + 128) * 32 * 4;   // 64 KB
    constexpr int SMEM64  = 2 * (128 + 64) * 32 * 4;    // 48 KB
    cudaFuncSetAttribute(mma_gemm_kernel<128, true>,
                         cudaFuncAttributeMaxDynamicSharedMemorySize, SMEM128);
    cudaFuncSetAttribute(mma_gemm_kernel<64, false>,
                         cudaFuncAttributeMaxDynamicSharedMemorySize, SMEM64);

    float* out = (float*)d_out;
    float* attn_all = out + (size_t)B_ * S_ * D_;   // x first, then attns

    // weight transposes (independent of everything else)
    {
        dim3 blk(32, 8);
        transpose_attn_kernel<<<dim3(16, 16, 16), blk>>>(Wq, Wk, Wv, Wo,
                                                         wT + WT_ATTN);
        transpose_c1_kernel<<<dim3(64, 16, 4), blk>>>(c1_w, wT + WT_C1);
        transpose_c2_kernel<<<dim3(16, 64, 4), blk>>>(c2_w, wT + WT_C2);
    }

    embed_kernel<<<(T_ * D_ + 255) / 256, 256>>>(enc, val_w, val_b, pos, x);

    const long SD  = (long)S_ * D_;
    const long SS  = (long)S_ * S_;
    const long HSS = (long)H_ * SS;

    for (int l = 0; l < L_; l++) {
        const float* WqT = wT + WT_ATTN + (long)(l * 4 + 0) * D_ * D_;
        const float* WkT = wT + WT_ATTN + (long)(l * 4 + 1) * D_ * D_;
        const float* WvT = wT + WT_ATTN + (long)(l * 4 + 2) * D_ * D_;
        const float* WoT = wT + WT_ATTN + (long)(l * 4 + 3) * D_ * D_;
        const float* c1T = wT + WT_C1 + (long)l * D_ * F_;   // [F, D]
        const float* c2T = wT + WT_C2 + (long)l * F_ * D_;   // [D, F]
        float* attnL = attn_all + (long)l * B_ * HSS;

        dim3 gProj(D_ / 128, T_ / 128, 1);   // (4,32)
        mma_gemm_kernel<128, true><<<gProj, 256, SMEM128>>>(
            x, WqT, q, bq + l * D_, D_, D_, D_, D_,
            0, 0, 0, 0, 0, 0, 1, 1.f, 0);
        mma_gemm_kernel<128, true><<<gProj, 256, SMEM128>>>(
            x, WkT, k, bk + l * D_, D_, D_, D_, D_,
            0, 0, 0, 0, 0, 0, 1, 1.f, 0);
        mma_gemm_kernel<128, true><<<gProj, 256, SMEM128>>>(
            x, WvT, v, bv + l * D_, D_, D_, D_, D_,
            0, 0, 0, 0, 0, 0, 1, 1.f, 0);

        // scores = Q_bh @ K_bh^T * scale  (straight into d_out slot)
        dim3 gScore(S_ / 128, S_ / 128, B_ * H_);   // (4,4,64)
        mma_gemm_kernel<128, true><<<gScore, 256, SMEM128>>>(
            q, k, attnL, nullptr, DK_, D_, D_, S_,
            SD, DK_, SD, DK_, HSS, SS, H_, SCALE_, 0);

        softmax512_kernel<<<B_ * H_ * S_, 256>>>(attnL);

        // ctx = attn @ V_bh   (non-transposed B, N = 64)
        dim3 gCtx(1, S_ / 128, B_ * H_);
        mma_gemm_kernel<64, false><<<gCtx, 256, SMEM64>>>(
            attnL, v, ctx, nullptr, S_, S_, D_, D_,
            HSS, SS, SD, DK_, SD, DK_, H_, 1.f, 0);

        // out proj + residual LN1
        mma_gemm_kernel<128, true><<<gProj, 256, SMEM128>>>(
            ctx, WoT, tmp, bo + l * D_, D_, D_, D_, D_,
            0, 0, 0, 0, 0, 0, 1, 1.f, 0);
        ln_residual_kernel<<<T_, 256>>>(tmp, x, ln1_g + l * D_, ln1_b + l * D_);

        // FFN
        dim3 gF1(F_ / 128, T_ / 128, 1);            // (16,32)
        mma_gemm_kernel<128, true><<<gF1, 256, SMEM128>>>(
            x, c1T, ffn, c1_b + l * F_, D_, D_, D_, F_,
            0, 0, 0, 0, 0, 0, 1, 1.f, 1);
        mma_gemm_kernel<128, true><<<gProj, 256, SMEM128>>>(
            ffn, c2T, tmp, c2_b + l * D_, F_, F_, F_, D_,
            0, 0, 0, 0, 0, 0, 1, 1.f, 0);
        ln_residual_kernel<<<T_, 256>>>(tmp, x, ln2_g + l * D_, ln2_b + l * D_);
    }

    int n4 = T_ * D_ / 4;
    copy4_kernel<<<(n4 + 255) / 256, 256>>>((const float4*)x, (float4*)out, n4);
}

// round 4
// speedup vs baseline: 4.5250x; 1.2814x over previous
#include <cuda_runtime.h>
#include <math.h>
#include <stdint.h>

// ---------------------------------------------------------------------------
// Problem constants
// ---------------------------------------------------------------------------
namespace {
constexpr int B_ = 8, S_ = 512, C_ = 12, D_ = 512, H_ = 8, F_ = 2048, L_ = 4;
constexpr int DK_ = D_ / H_;          // 64
constexpr int T_  = B_ * S_;          // 4096 tokens
constexpr float EPS_ = 1e-5f;
constexpr float SCALE_ = 0.125f;      // 1/sqrt(64)
}

// ---------------------------------------------------------------------------
// Scratch (static device globals -- no allocations allowed)
// ---------------------------------------------------------------------------
__device__ float g_x   [T_ * D_];
__device__ float g_qkv [3 * T_ * D_];
__device__ float g_vT  [T_ * D_];
__device__ float g_ctx [T_ * D_];
__device__ float g_tmp [T_ * D_];
__device__ float g_ffn [T_ * F_];
__device__ float g_bias[3 * L_ * D_];
// transposed weights: [16 x 512x512 attn] [4 x 2048x512 c1T] [4 x 512x2048 c2T]
__device__ float g_wT  [12582912];

namespace {
constexpr long WT_ATTN = 0;                 // (l*4+m)*262144
constexpr long WT_C1   = 4194304;           // + l*1048576
constexpr long WT_C2   = 8388608;           // + l*1048576
}

// ---------------------------------------------------------------------------
// Embedding: x = enc @ val_w + val_b + pos
// ---------------------------------------------------------------------------
__global__ void embed_kernel(const float* __restrict__ enc,
                             const float* __restrict__ vw,
                             const float* __restrict__ vb,
                             const float* __restrict__ pos,
                             float* __restrict__ x) {
    int idx = blockIdx.x * blockDim.x + threadIdx.x;
    if (idx >= T_ * D_) return;
    int t = idx >> 9;
    int d = idx & (D_ - 1);
    int s = t & (S_ - 1);
    float acc = vb[d] + pos[s * D_ + d];
    const float* e = enc + t * C_;
#pragma unroll
    for (int c = 0; c < C_; c++) acc = fmaf(e[c], vw[c * D_ + d], acc);
    x[idx] = acc;
}

// ---------------------------------------------------------------------------
// Transpose helpers
// ---------------------------------------------------------------------------
__device__ __forceinline__ void transpose_tile(const float* __restrict__ src,
                                               float* __restrict__ dst,
                                               int R, int C) {
    __shared__ float sh[32][33];
    int x  = blockIdx.x * 32 + threadIdx.x;
    int y0 = blockIdx.y * 32 + threadIdx.y;
#pragma unroll
    for (int i = 0; i < 4; i++)
        sh[threadIdx.y + i * 8][threadIdx.x] = src[(long)(y0 + i * 8) * C + x];
    __syncthreads();
    int xo  = blockIdx.y * 32 + threadIdx.x;
    int yo0 = blockIdx.x * 32 + threadIdx.y;
#pragma unroll
    for (int i = 0; i < 4; i++)
        dst[(long)(yo0 + i * 8) * R + xo] = sh[threadIdx.x][threadIdx.y + i * 8];
}

__global__ void transpose_attn_kernel(const float* __restrict__ Wq,
                                      const float* __restrict__ Wk,
                                      const float* __restrict__ Wv,
                                      const float* __restrict__ Wo,
                                      float* __restrict__ dst) {
    int z = blockIdx.z, l = z >> 2, m = z & 3;
    const float* src = (m == 0) ? Wq : (m == 1) ? Wk : (m == 2) ? Wv : Wo;
    src += (long)l * D_ * D_;
    transpose_tile(src, dst + (long)z * D_ * D_, D_, D_);
}

__global__ void transpose_c1_kernel(const float* __restrict__ c1,
                                    float* __restrict__ dst) {
    int l = blockIdx.z;
    transpose_tile(c1 + (long)l * D_ * F_, dst + (long)l * D_ * F_, D_, F_);
}

__global__ void transpose_c2_kernel(const float* __restrict__ c2,
                                    float* __restrict__ dst) {
    int l = blockIdx.z;
    transpose_tile(c2 + (long)l * F_ * D_, dst + (long)l * F_ * D_, F_, D_);
}

// v [B,S,H,DK] (i.e. [T,D]) -> vT [B,H,DK,S]
__global__ void transpose_v_kernel(const float* __restrict__ v,
                                   float* __restrict__ vT) {
    __shared__ float sh[32][33];
    int z = blockIdx.z;                   // b*H + h
    int b = z >> 3, h = z & 7;
    const float* src = v + (long)b * S_ * D_ + h * DK_;   // [S,DK], stride D
    float* dst = vT + (long)z * DK_ * S_;                 // [DK,S], stride S
    int s0 = blockIdx.y * 32, d0 = blockIdx.x * 32;
#pragma unroll
    for (int i = 0; i < 4; i++)
        sh[threadIdx.y + i * 8][threadIdx.x] =
            src[(long)(s0 + threadIdx.y + i * 8) * D_ + d0 + threadIdx.x];
    __syncthreads();
#pragma unroll
    for (int i = 0; i < 4; i++)
        dst[(long)(d0 + threadIdx.y + i * 8) * S_ + s0 + threadIdx.x] =
            sh[threadIdx.x][threadIdx.y + i * 8];
}

__global__ void pack_bias_kernel(const float* __restrict__ bq,
                                 const float* __restrict__ bk,
                                 const float* __restrict__ bv,
                                 float* __restrict__ dst) {
    int i = blockIdx.x * blockDim.x + threadIdx.x;
    if (i >= 3 * L_ * D_) return;
    int z = i / (L_ * D_), r = i % (L_ * D_);
    const float* s = (z == 0) ? bq : (z == 1) ? bk : bv;
    dst[i] = s[r];
}

// ---------------------------------------------------------------------------
// Reductions (block = 256)
// ---------------------------------------------------------------------------
__device__ __forceinline__ float warpReduceSum(float v) {
#pragma unroll
    for (int o = 16; o > 0; o >>= 1) v += __shfl_xor_sync(0xffffffffu, v, o);
    return v;
}
__device__ __forceinline__ float warpReduceMax(float v) {
#pragma unroll
    for (int o = 16; o > 0; o >>= 1) v = fmaxf(v, __shfl_xor_sync(0xffffffffu, v, o));
    return v;
}
__device__ __forceinline__ float blockReduceSum(float v, float* sh) {
    int lane = threadIdx.x & 31, wid = threadIdx.x >> 5;
    v = warpReduceSum(v);
    __syncthreads();
    if (lane == 0) sh[wid] = v;
    __syncthreads();
    if (wid == 0) {
        float t = (lane < 8) ? sh[lane] : 0.f;
        t = warpReduceSum(t);
        if (lane == 0) sh[0] = t;
    }
    __syncthreads();
    return sh[0];
}
__device__ __forceinline__ float blockReduceMax(float v, float* sh) {
    int lane = threadIdx.x & 31, wid = threadIdx.x >> 5;
    v = warpReduceMax(v);
    __syncthreads();
    if (lane == 0) sh[wid] = v;
    __syncthreads();
    if (wid == 0) {
        float t = (lane < 8) ? sh[lane] : -INFINITY;
        t = warpReduceMax(t);
        if (lane == 0) sh[0] = t;
    }
    __syncthreads();
    return sh[0];
}

// ---------------------------------------------------------------------------
// Softmax over rows of length 512, in place. grid = numRows, block = 256.
// ---------------------------------------------------------------------------
__global__ void softmax512_kernel(float* __restrict__ data) {
    __shared__ float sh[32];
    float* p = data + (size_t)blockIdx.x * 512;
    int t = threadIdx.x;
    float v0 = p[t], v1 = p[t + 256];
    float m = blockReduceMax(fmaxf(v0, v1), sh);
    float e0 = expf(v0 - m), e1 = expf(v1 - m);
    float s = blockReduceSum(e0 + e1, sh);
    float inv = 1.f / s;
    p[t]       = e0 * inv;
    p[t + 256] = e1 * inv;
}

// ---------------------------------------------------------------------------
// Residual add + LayerNorm: x = LN(y + x) * g + b. block=256.
// ---------------------------------------------------------------------------
__global__ void ln_residual_kernel(const float* __restrict__ y,
                                   float* __restrict__ x,
                                   const float* __restrict__ g,
                                   const float* __restrict__ b) {
    __shared__ float sh[32];
    size_t base = (size_t)blockIdx.x * 512;
    int t = threadIdx.x;
    float s0 = y[base + t]       + x[base + t];
    float s1 = y[base + t + 256] + x[base + t + 256];
    float mean = blockReduceSum(s0 + s1, sh) * (1.f / 512.f);
    float d0 = s0 - mean, d1 = s1 - mean;
    float var = blockReduceSum(d0 * d0 + d1 * d1, sh) * (1.f / 512.f);
    float rs = rsqrtf(var + EPS_);
    x[base + t]       = d0 * rs * g[t]       + b[t];
    x[base + t + 256] = d1 * rs * g[t + 256] + b[t + 256];
}

// ---------------------------------------------------------------------------
// TF32 tensor-core batched-strided GEMM (TB only: B is [N,K] row-major).
//   C = alpha * A @ B^T + bias (+relu)
// Block tile 128 x BN, BK=32, 3-stage cp.async pipeline, 256 threads,
// 8 warps (4x2), warp tile 32x(BN/2). Raw fp32 bits fed to mma.tf32
// (implicit RZ truncation to tf32).
// ---------------------------------------------------------------------------
__device__ __forceinline__ void cp_async16(uint32_t smem, const void* g) {
    asm volatile("cp.async.cg.shared.global [%0], [%1], 16;"
                 :: "r"(smem), "l"(g));
}

template <int BN>
__global__ __launch_bounds__(256, 2) void mma_gemm_kernel(
    const float* __restrict__ Ag, const float* __restrict__ Bg,
    float* __restrict__ Cg, const float* __restrict__ bias,
    int K, int lda, int ldb, int ldc,
    long aO, long aI, long bO, long bI, long cO, long cI, int bH,
    long biasStride, float alpha, int relu) {
    constexpr int BM = 128, BK = 32, STAGES = 3;
    constexpr int JT = (BN / 2) / 8;          // n-tiles per warp (8 or 4)
    constexpr int ASZ = BM * BK;              // u32 per A stage
    constexpr int BSZ = BN * BK;

    extern __shared__ uint32_t smem[];
    uint32_t* sA = smem;                      // [STAGES][ASZ]
    uint32_t* sB = smem + STAGES * ASZ;       // [STAGES][BSZ]

    const int z = blockIdx.z;
    Ag += (long)(z / bH) * aO + (long)(z % bH) * aI;
    Bg += (long)(z / bH) * bO + (long)(z % bH) * bI;
    Cg += (long)(z / bH) * cO + (long)(z % bH) * cI;
    if (bias) bias += (long)(z / bH) * biasStride;

    const int tid  = threadIdx.x;
    const int lane = tid & 31;
    const int warp = tid >> 5;
    const int brow = blockIdx.y * BM;
    const int bcol = blockIdx.x * BN;
    const int warpM = (warp >> 1) * 32;       // 4 warps along M
    const int warpN = (warp & 1) * (BN / 2);  // 2 warps along N

    const uint32_t aBase = (uint32_t)__cvta_generic_to_shared(sA);
    const uint32_t bBase = (uint32_t)__cvta_generic_to_shared(sB);

    float acc[2][JT][4];
#pragma unroll
    for (int i = 0; i < 2; i++)
#pragma unroll
        for (int j = 0; j < JT; j++)
#pragma unroll
            for (int c = 0; c < 4; c++) acc[i][j][c] = 0.f;

    const int aRow   = tid >> 3;              // 0..31
    const int aChunk = tid & 7;               // 16B chunk in 32-float row

    auto load_stage = [&](int t, int buf) {
        const uint32_t aBuf = aBase + (uint32_t)buf * ASZ * 4;
        const uint32_t bBuf = bBase + (uint32_t)buf * BSZ * 4;
        const uint32_t swOff = (((uint32_t)aChunk ^ (aRow & 7)) << 2);
#pragma unroll
        for (int i = 0; i < 4; i++) {
            int row = aRow + i * 32;
            cp_async16(aBuf + (row * BK + swOff) * 4,
                       &Ag[(long)(brow + row) * lda + t * BK + aChunk * 4]);
        }
#pragma unroll
        for (int i = 0; i < BN / 32; i++) {
            int row = aRow + i * 32;
            cp_async16(bBuf + (row * BK + swOff) * 4,
                       &Bg[(long)(bcol + row) * ldb + t * BK + aChunk * 4]);
        }
    };

    auto compute = [&](int buf) {
        const uint32_t aB = aBase + (uint32_t)buf * ASZ * 4;
        const uint32_t bB = bBase + (uint32_t)buf * BSZ * 4;
#pragma unroll
        for (int ks = 0; ks < 4; ks++) {
            uint32_t af[2][4];
            uint32_t bf[JT][2];
#pragma unroll
            for (int i = 0; i < 2; i++) {
                int sub = lane >> 3, r = lane & 7;
                int row = warpM + i * 16 + (sub & 1) * 8 + r;
                int chunk = ks * 2 + (sub >> 1);
                uint32_t off = row * BK + (((uint32_t)chunk ^ (row & 7)) << 2);
                uint32_t addr = aB + off * 4;
                asm volatile(
                    "ldmatrix.sync.aligned.m8n8.x4.shared.b16 {%0,%1,%2,%3}, [%4];"
                    : "=r"(af[i][0]), "=r"(af[i][1]), "=r"(af[i][2]), "=r"(af[i][3])
                    : "r"(addr));
            }
#pragma unroll
            for (int jp = 0; jp < JT / 2; jp++) {
                int r = lane & 7;
                int row = warpN + jp * 16 + ((lane >> 4) & 1) * 8 + r;
                int chunk = ks * 2 + ((lane >> 3) & 1);
                uint32_t off = row * BK + (((uint32_t)chunk ^ (row & 7)) << 2);
                uint32_t addr = bB + off * 4;
                asm volatile(
                    "ldmatrix.sync.aligned.m8n8.x4.shared.b16 {%0,%1,%2,%3}, [%4];"
                    : "=r"(bf[2 * jp][0]), "=r"(bf[2 * jp][1]),
                      "=r"(bf[2 * jp + 1][0]), "=r"(bf[2 * jp + 1][1])
                    : "r"(addr));
            }
#pragma unroll
            for (int i = 0; i < 2; i++)
#pragma unroll
                for (int j = 0; j < JT; j++) {
                    asm volatile(
                        "mma.sync.aligned.m16n8k8.row.col.f32.tf32.tf32.f32 "
                        "{%0,%1,%2,%3}, {%4,%5,%6,%7}, {%8,%9}, {%0,%1,%2,%3};"
                        : "+f"(acc[i][j][0]), "+f"(acc[i][j][1]),
                          "+f"(acc[i][j][2]), "+f"(acc[i][j][3])
                        : "r"(af[i][0]), "r"(af[i][1]), "r"(af[i][2]),
                          "r"(af[i][3]), "r"(bf[j][0]), "r"(bf[j][1]));
                }
        }
    };

    const int nk = K / BK;
    // prologue: STAGES-1 groups
    load_stage(0, 0);
    asm volatile("cp.async.commit_group;");
    if (nk > 1) load_stage(1, 1);
    asm volatile("cp.async.commit_group;");

#pragma unroll 1
    for (int t = 0; t < nk; t++) {
        asm volatile("cp.async.wait_group 1;");
        __syncthreads();
        int nt = t + STAGES - 1;
        if (nt < nk) load_stage(nt, nt % STAGES);
        asm volatile("cp.async.commit_group;");
        compute(t % STAGES);
    }

    // epilogue
    const int g  = lane >> 2;
    const int tg = lane & 3;
#pragma unroll
    for (int i = 0; i < 2; i++) {
#pragma unroll
        for (int j = 0; j < JT; j++) {
            int col = bcol + warpN + j * 8 + tg * 2;
            float b0 = 0.f, b1 = 0.f;
            if (bias) { b0 = bias[col]; b1 = bias[col + 1]; }
            int row0 = brow + warpM + i * 16 + g;
            float v0 = acc[i][j][0] * alpha + b0;
            float v1 = acc[i][j][1] * alpha + b1;
            float v2 = acc[i][j][2] * alpha + b0;
            float v3 = acc[i][j][3] * alpha + b1;
            if (relu) {
                v0 = fmaxf(v0, 0.f); v1 = fmaxf(v1, 0.f);
                v2 = fmaxf(v2, 0.f); v3 = fmaxf(v3, 0.f);
            }
            *reinterpret_cast<float2*>(&Cg[(long)row0 * ldc + col]) =
                make_float2(v0, v1);
            *reinterpret_cast<float2*>(&Cg[(long)(row0 + 8) * ldc + col]) =
                make_float2(v2, v3);
        }
    }
}

// ---------------------------------------------------------------------------
// Final copy x -> d_out (float4)
// ---------------------------------------------------------------------------
__global__ void copy4_kernel(const float4* __restrict__ src,
                             float4* __restrict__ dst, int n4) {
    int i = blockIdx.x * blockDim.x + threadIdx.x;
    if (i < n4) dst[i] = src[i];
}

// ---------------------------------------------------------------------------
// Host launcher
// ---------------------------------------------------------------------------
extern "C" void kernel_launch(void* const* d_in, const int* in_sizes, int n_in,
                              void* d_out, int out_size) {
    const float* enc   = (const float*)d_in[0];
    const float* val_w = (const float*)d_in[1];
    const float* val_b = (const float*)d_in[2];
    const float* pos   = (const float*)d_in[3];
    const float* Wq    = (const float*)d_in[4];
    const float* bq    = (const float*)d_in[5];
    const float* Wk    = (const float*)d_in[6];
    const float* bk    = (const float*)d_in[7];
    const float* Wv    = (const float*)d_in[8];
    const float* bv    = (const float*)d_in[9];
    const float* Wo    = (const float*)d_in[10];
    const float* bo    = (const float*)d_in[11];
    const float* ln1_g = (const float*)d_in[12];
    const float* ln1_b = (const float*)d_in[13];
    const float* c1_w  = (const float*)d_in[14];
    const float* c1_b  = (const float*)d_in[15];
    const float* c2_w  = (const float*)d_in[16];
    const float* c2_b  = (const float*)d_in[17];
    const float* ln2_g = (const float*)d_in[18];
    const float* ln2_b = (const float*)d_in[19];

    float *x, *qkv, *vT, *ctx, *tmp, *ffn, *wT, *bias3;
    cudaGetSymbolAddress((void**)&x,    g_x);
    cudaGetSymbolAddress((void**)&qkv,  g_qkv);
    cudaGetSymbolAddress((void**)&vT,   g_vT);
    cudaGetSymbolAddress((void**)&ctx,  g_ctx);
    cudaGetSymbolAddress((void**)&tmp,  g_tmp);
    cudaGetSymbolAddress((void**)&ffn,  g_ffn);
    cudaGetSymbolAddress((void**)&wT,   g_wT);
    cudaGetSymbolAddress((void**)&bias3, g_bias);

    constexpr int SMEM128 = 3 * (128 + 128) * 32 * 4;   // 96 KB
    constexpr int SMEM64  = 3 * (128 + 64) * 32 * 4;    // 72 KB
    cudaFuncSetAttribute(mma_gemm_kernel<128>,
                         cudaFuncAttributeMaxDynamicSharedMemorySize, SMEM128);
    cudaFuncSetAttribute(mma_gemm_kernel<64>,
                         cudaFuncAttributeMaxDynamicSharedMemorySize, SMEM64);

    float* out = (float*)d_out;
    float* attn_all = out + (size_t)B_ * S_ * D_;   // x first, then attns

    // one-time per call: weight transposes + bias pack (independent)
    {
        dim3 blk(32, 8);
        transpose_attn_kernel<<<dim3(16, 16, 16), blk>>>(Wq, Wk, Wv, Wo,
                                                         wT + WT_ATTN);
        transpose_c1_kernel<<<dim3(64, 16, 4), blk>>>(c1_w, wT + WT_C1);
        transpose_c2_kernel<<<dim3(16, 64, 4), blk>>>(c2_w, wT + WT_C2);
        pack_bias_kernel<<<(3 * L_ * D_ + 255) / 256, 256>>>(bq, bk, bv, bias3);
    }

    embed_kernel<<<(T_ * D_ + 255) / 256, 256>>>(enc, val_w, val_b, pos, x);

    const long TD  = (long)T_ * D_;
    const long SD  = (long)S_ * D_;
    const long SS  = (long)S_ * S_;
    const long HSS = (long)H_ * SS;

    float* q = qkv;
    float* k = qkv + TD;
    float* v = qkv + 2 * TD;

    for (int l = 0; l < L_; l++) {
        const float* WqkvT = wT + WT_ATTN + (long)(l * 4) * D_ * D_;  // q,k,v contig
        const float* WoT = wT + WT_ATTN + (long)(l * 4 + 3) * D_ * D_;
        const float* c1T = wT + WT_C1 + (long)l * D_ * F_;   // [F, D]
        const float* c2T = wT + WT_C2 + (long)l * F_ * D_;   // [D, F]
        float* attnL = attn_all + (long)l * B_ * HSS;

        // fused Q/K/V projection: z batches over the 3 weight matrices
        dim3 gQKV(D_ / 128, T_ / 128, 3);   // 384 CTAs
        mma_gemm_kernel<128><<<gQKV, 256, SMEM128>>>(
            x, WqkvT, qkv, bias3 + l * D_, D_, D_, D_, D_,
            0, 0, (long)D_ * D_, 0, TD, 0, 1, (long)L_ * D_, 1.f, 0);

        // V -> [B,H,DK,S]
        transpose_v_kernel<<<dim3(2, 16, 64), dim3(32, 8)>>>(v, vT);

        // scores = Q_bh @ K_bh^T * scale  (straight into d_out slot)
        dim3 gScore(S_ / 128, S_ / 128, B_ * H_);   // 1024 CTAs
        mma_gemm_kernel<128><<<gScore, 256, SMEM128>>>(
            q, k, attnL, nullptr, DK_, D_, D_, S_,
            SD, DK_, SD, DK_, HSS, SS, H_, 0, SCALE_, 0);

        softmax512_kernel<<<B_ * H_ * S_, 256>>>(attnL);

        // ctx = attn @ V_bh  (vT rows are [dk, s] -> TB path)
        dim3 gCtx(1, S_ / 128, B_ * H_);            // 256 CTAs
        mma_gemm_kernel<64><<<gCtx, 256, SMEM64>>>(
            attnL, vT, ctx, nullptr, S_, S_, S_, D_,
            HSS, SS, SD, (long)DK_ * S_, SD, DK_, H_, 0, 1.f, 0);

        // out proj (BN=64 for fill) + residual LN1
        dim3 gOP(D_ / 64, T_ / 128, 1);             // 256 CTAs
        mma_gemm_kernel<64><<<gOP, 256, SMEM64>>>(
            ctx, WoT, tmp, bo + l * D_, D_, D_, D_, D_,
            0, 0, 0, 0, 0, 0, 1, 0, 1.f, 0);
        ln_residual_kernel<<<T_, 256>>>(tmp, x, ln1_g + l * D_, ln1_b + l * D_);

        // FFN
        dim3 gF1(F_ / 128, T_ / 128, 1);            // 512 CTAs
        mma_gemm_kernel<128><<<gF1, 256, SMEM128>>>(
            x, c1T, ffn, c1_b + l * F_, D_, D_, D_, F_,
            0, 0, 0, 0, 0, 0, 1, 0, 1.f, 1);
        dim3 gF2(D_ / 64, T_ / 128, 1);             // 256 CTAs
        mma_gemm_kernel<64><<<gF2, 256, SMEM64>>>(
            ffn, c2T, tmp, c2_b + l * D_, F_, F_, F_, D_,
            0, 0, 0, 0, 0, 0, 1, 0, 1.f, 0);
        ln_residual_kernel<<<T_, 256>>>(tmp, x, ln2_g + l * D_, ln2_b + l * D_);
    }

    int n4 = T_ * D_ / 4;
    copy4_kernel<<<(n4 + 255) / 256, 256>>>((const float4*)x, (float4*)out, n4);
}

// round 7
// speedup vs baseline: 7.1713x; 1.5848x over previous
#include <cuda_runtime.h>
#include <cuda_fp16.h>
#include <math.h>
#include <stdint.h>

// ---------------------------------------------------------------------------
// Problem constants
// ---------------------------------------------------------------------------
namespace {
constexpr int B_ = 8, S_ = 512, C_ = 12, D_ = 512, H_ = 8, F_ = 2048, L_ = 4;
constexpr int DK_ = D_ / H_;          // 64
constexpr int T_  = B_ * S_;          // 4096 tokens
constexpr float EPS_ = 1e-5f;
constexpr float SCALE_ = 0.125f;      // 1/sqrt(64)
}

// ---------------------------------------------------------------------------
// Scratch (static device globals -- no allocations allowed)
// ---------------------------------------------------------------------------
__device__ float  g_x   [T_ * D_];          // fp32 residual stream
__device__ float  g_tmp [T_ * D_];          // fp32 GEMM out for LN residual
__device__ float  g_bias[3 * L_ * D_];
__device__ __half g_xh  [T_ * D_];          // fp16 copy of x (GEMM input)
__device__ __half g_qkv [3 * T_ * D_];
__device__ __half g_vT  [T_ * D_];
__device__ __half g_ctx [T_ * D_];
__device__ __half g_ffn [T_ * F_];
__device__ __half g_attnh[(size_t)B_ * H_ * S_ * S_];   // fp16 attn (per layer)
// transposed fp16 weights: [16 x 512x512 attn][4 x 2048x512 c1T][4 x 512x2048 c2T]
__device__ __half g_wTh [12582912];

namespace {
constexpr long WT_ATTN = 0;
constexpr long WT_C1   = 4194304;
constexpr long WT_C2   = 8388608;
}

// ---------------------------------------------------------------------------
// Embedding: x = enc @ val_w + val_b + pos  (fp32 out + fp16 copy)
// ---------------------------------------------------------------------------
__global__ void embed_kernel(const float* __restrict__ enc,
                             const float* __restrict__ vw,
                             const float* __restrict__ vb,
                             const float* __restrict__ pos,
                             float* __restrict__ x,
                             __half* __restrict__ xh) {
    int idx = blockIdx.x * blockDim.x + threadIdx.x;
    if (idx >= T_ * D_) return;
    int t = idx >> 9;
    int d = idx & (D_ - 1);
    int s = t & (S_ - 1);
    float acc = vb[d] + pos[s * D_ + d];
    const float* e = enc + t * C_;
#pragma unroll
    for (int c = 0; c < C_; c++) acc = fmaf(e[c], vw[c * D_ + d], acc);
    x[idx]  = acc;
    xh[idx] = __float2half_rn(acc);
}

// ---------------------------------------------------------------------------
// Weight transpose + fp32 -> fp16 convert
// ---------------------------------------------------------------------------
__device__ __forceinline__ void transpose_tile_h(const float* __restrict__ src,
                                                 __half* __restrict__ dst,
                                                 int R, int C) {
    __shared__ float sh[32][33];
    int x  = blockIdx.x * 32 + threadIdx.x;
    int y0 = blockIdx.y * 32 + threadIdx.y;
#pragma unroll
    for (int i = 0; i < 4; i++)
        sh[threadIdx.y + i * 8][threadIdx.x] = src[(long)(y0 + i * 8) * C + x];
    __syncthreads();
    int xo  = blockIdx.y * 32 + threadIdx.x;
    int yo0 = blockIdx.x * 32 + threadIdx.y;
#pragma unroll
    for (int i = 0; i < 4; i++)
        dst[(long)(yo0 + i * 8) * R + xo] =
            __float2half_rn(sh[threadIdx.x][threadIdx.y + i * 8]);
}

__global__ void transpose_attn_kernel(const float* __restrict__ Wq,
                                      const float* __restrict__ Wk,
                                      const float* __restrict__ Wv,
                                      const float* __restrict__ Wo,
                                      __half* __restrict__ dst) {
    int z = blockIdx.z, l = z >> 2, m = z & 3;
    const float* src = (m == 0) ? Wq : (m == 1) ? Wk : (m == 2) ? Wv : Wo;
    src += (long)l * D_ * D_;
    transpose_tile_h(src, dst + (long)z * D_ * D_, D_, D_);
}

__global__ void transpose_c1_kernel(const float* __restrict__ c1,
                                    __half* __restrict__ dst) {
    int l = blockIdx.z;
    transpose_tile_h(c1 + (long)l * D_ * F_, dst + (long)l * D_ * F_, D_, F_);
}

__global__ void transpose_c2_kernel(const float* __restrict__ c2,
                                    __half* __restrict__ dst) {
    int l = blockIdx.z;
    transpose_tile_h(c2 + (long)l * F_ * D_, dst + (long)l * F_ * D_, F_, D_);
}

// v [B,S,H,DK] fp16 -> vT [B,H,DK,S] fp16
__global__ void transpose_v_kernel(const __half* __restrict__ v,
                                   __half* __restrict__ vT) {
    __shared__ __half sh[32][34];
    int z = blockIdx.z;                   // b*H + h
    int b = z >> 3, h = z & 7;
    const __half* src = v + (long)b * S_ * D_ + h * DK_;   // [S,DK], stride D
    __half* dst = vT + (long)z * DK_ * S_;                 // [DK,S], stride S
    int s0 = blockIdx.y * 32, d0 = blockIdx.x * 32;
#pragma unroll
    for (int i = 0; i < 4; i++)
        sh[threadIdx.y + i * 8][threadIdx.x] =
            src[(long)(s0 + threadIdx.y + i * 8) * D_ + d0 + threadIdx.x];
    __syncthreads();
#pragma unroll
    for (int i = 0; i < 4; i++)
        dst[(long)(d0 + threadIdx.y + i * 8) * S_ + s0 + threadIdx.x] =
            sh[threadIdx.x][threadIdx.y + i * 8];
}

__global__ void pack_bias_kernel(const float* __restrict__ bq,
                                 const float* __restrict__ bk,
                                 const float* __restrict__ bv,
                                 float* __restrict__ dst) {
    int i = blockIdx.x * blockDim.x + threadIdx.x;
    if (i >= 3 * L_ * D_) return;
    int z = i / (L_ * D_), r = i % (L_ * D_);
    const float* s = (z == 0) ? bq : (z == 1) ? bk : bv;
    dst[i] = s[r];
}

// ---------------------------------------------------------------------------
// Reductions over 4 warps (block = 128)
// ---------------------------------------------------------------------------
__device__ __forceinline__ float warpReduceSum(float v) {
#pragma unroll
    for (int o = 16; o > 0; o >>= 1) v += __shfl_xor_sync(0xffffffffu, v, o);
    return v;
}
__device__ __forceinline__ float warpReduceMax(float v) {
#pragma unroll
    for (int o = 16; o > 0; o >>= 1) v = fmaxf(v, __shfl_xor_sync(0xffffffffu, v, o));
    return v;
}
__device__ __forceinline__ float blockReduceSum4(float v, float* sh) {
    int lane = threadIdx.x & 31, wid = threadIdx.x >> 5;
    v = warpReduceSum(v);
    __syncthreads();
    if (lane == 0) sh[wid] = v;
    __syncthreads();
    float t = sh[0] + sh[1] + sh[2] + sh[3];
    return t;
}
__device__ __forceinline__ float blockReduceMax4(float v, float* sh) {
    int lane = threadIdx.x & 31, wid = threadIdx.x >> 5;
    v = warpReduceMax(v);
    __syncthreads();
    if (lane == 0) sh[wid] = v;
    __syncthreads();
    return fmaxf(fmaxf(sh[0], sh[1]), fmaxf(sh[2], sh[3]));
}

// ---------------------------------------------------------------------------
// Softmax over rows of 512, in place (fp32) + fp16 copy. grid=rows, block=128.
// ---------------------------------------------------------------------------
__global__ void softmax512_kernel(float* __restrict__ data,
                                  __half* __restrict__ outh) {
    __shared__ float sh[4];
    size_t base = (size_t)blockIdx.x * 512;
    int t = threadIdx.x;
    float4 v = reinterpret_cast<float4*>(data + base)[t];
    float m = blockReduceMax4(fmaxf(fmaxf(v.x, v.y), fmaxf(v.z, v.w)), sh);
    float e0 = expf(v.x - m), e1 = expf(v.y - m);
    float e2 = expf(v.z - m), e3 = expf(v.w - m);
    float s = blockReduceSum4(e0 + e1 + e2 + e3, sh);
    float inv = 1.f / s;
    e0 *= inv; e1 *= inv; e2 *= inv; e3 *= inv;
    reinterpret_cast<float4*>(data + base)[t] = make_float4(e0, e1, e2, e3);
    __half2* hp = reinterpret_cast<__half2*>(outh + base + t * 4);
    hp[0] = __floats2half2_rn(e0, e1);
    hp[1] = __floats2half2_rn(e2, e3);
}

// ---------------------------------------------------------------------------
// Residual add + LayerNorm: x = LN(y + x)*g + b; also fp16 copy. block=128.
// ---------------------------------------------------------------------------
__global__ void ln_residual_kernel(const float* __restrict__ y,
                                   float* __restrict__ x,
                                   __half* __restrict__ xh,
                                   const float* __restrict__ g,
                                   const float* __restrict__ b) {
    __shared__ float sh[4];
    size_t base = (size_t)blockIdx.x * 512;
    int t = threadIdx.x;
    float4 yv = reinterpret_cast<const float4*>(y + base)[t];
    float4 xv = reinterpret_cast<float4*>(x + base)[t];
    float s0 = yv.x + xv.x, s1 = yv.y + xv.y;
    float s2 = yv.z + xv.z, s3 = yv.w + xv.w;
    float mean = blockReduceSum4(s0 + s1 + s2 + s3, sh) * (1.f / 512.f);
    float d0 = s0 - mean, d1 = s1 - mean, d2 = s2 - mean, d3 = s3 - mean;
    __syncthreads();
    float var = blockReduceSum4(d0 * d0 + d1 * d1 + d2 * d2 + d3 * d3, sh) *
                (1.f / 512.f);
    float rs = rsqrtf(var + EPS_);
    float4 gv = reinterpret_cast<const float4*>(g)[t];
    float4 bv = reinterpret_cast<const float4*>(b)[t];
    float o0 = d0 * rs * gv.x + bv.x;
    float o1 = d1 * rs * gv.y + bv.y;
    float o2 = d2 * rs * gv.z + bv.z;
    float o3 = d3 * rs * gv.w + bv.w;
    reinterpret_cast<float4*>(x + base)[t] = make_float4(o0, o1, o2, o3);
    __half2* hp = reinterpret_cast<__half2*>(xh + base + t * 4);
    hp[0] = __floats2half2_rn(o0, o1);
    hp[1] = __floats2half2_rn(o2, o3);
}

// ---------------------------------------------------------------------------
// FP16 tensor-core batched-strided GEMM (B is [N,K] row-major, fp16).
//   C = alpha * A @ B^T + bias (+relu), fp32 accumulate, OutT in {float, half}.
// Block tile 128 x BN, BK=64 halves, 3-stage cp.async, 256 threads,
// 8 warps (4x2), warp tile 32x(BN/2), mma.m16n8k16.f16.
// ---------------------------------------------------------------------------
__device__ __forceinline__ void cp_async16(uint32_t smem, const void* g) {
    asm volatile("cp.async.cg.shared.global [%0], [%1], 16;"
                 :: "r"(smem), "l"(g));
}

__device__ __forceinline__ void store_pair(float* p, float a, float b) {
    *reinterpret_cast<float2*>(p) = make_float2(a, b);
}
__device__ __forceinline__ void store_pair(__half* p, float a, float b) {
    *reinterpret_cast<__half2*>(p) = __floats2half2_rn(a, b);
}

template <int BN, typename OutT>
__global__ __launch_bounds__(256, 2) void hgemm_kernel(
    const __half* __restrict__ Ag, const __half* __restrict__ Bg,
    OutT* __restrict__ Cg, const float* __restrict__ bias,
    int K, int lda, int ldb, int ldc,
    long aO, long aI, long bO, long bI, long cO, long cI, int bH,
    long biasStride, float alpha, int relu) {
    constexpr int BM = 128, BK = 64, STAGES = 3;
    constexpr int JT = (BN / 2) / 8;            // n8 tiles per warp
    constexpr int ASZB = BM * BK * 2;           // bytes per A stage (16KB)
    constexpr int BSZB = BN * BK * 2;

    extern __shared__ uint8_t smem[];

    const int z = blockIdx.z;
    Ag += (long)(z / bH) * aO + (long)(z % bH) * aI;
    Bg += (long)(z / bH) * bO + (long)(z % bH) * bI;
    Cg += (long)(z / bH) * cO + (long)(z % bH) * cI;
    if (bias) bias += (long)(z / bH) * biasStride;

    const int tid  = threadIdx.x;
    const int lane = tid & 31;
    const int warp = tid >> 5;
    const int brow = blockIdx.y * BM;
    const int bcol = blockIdx.x * BN;
    const int warpM = (warp >> 1) * 32;         // 4 warps along M
    const int warpN = (warp & 1) * (BN / 2);    // 2 warps along N

    const uint32_t aBase = (uint32_t)__cvta_generic_to_shared(smem);
    const uint32_t bBase = aBase + STAGES * ASZB;

    float acc[2][JT][4];
#pragma unroll
    for (int i = 0; i < 2; i++)
#pragma unroll
        for (int j = 0; j < JT; j++)
#pragma unroll
            for (int c = 0; c < 4; c++) acc[i][j][c] = 0.f;

    const int aRow   = tid >> 3;                // 0..31
    const int aChunk = tid & 7;                 // 16B chunk in 128B row

    auto load_stage = [&](int t, int buf) {
        const uint32_t aBuf = aBase + (uint32_t)buf * ASZB;
        const uint32_t bBuf = bBase + (uint32_t)buf * BSZB;
#pragma unroll
        for (int i = 0; i < 4; i++) {
            int row = aRow + i * 32;
            uint32_t off = row * 128 + (((uint32_t)aChunk ^ (row & 7)) << 4);
            cp_async16(aBuf + off,
                       &Ag[(long)(brow + row) * lda + t * BK + aChunk * 8]);
        }
#pragma unroll
        for (int i = 0; i < BN / 32; i++) {
            int row = aRow + i * 32;
            uint32_t off = row * 128 + (((uint32_t)aChunk ^ (row & 7)) << 4);
            cp_async16(bBuf + off,
                       &Bg[(long)(bcol + row) * ldb + t * BK + aChunk * 8]);
        }
    };

    auto compute = [&](int buf) {
        const uint32_t aB = aBase + (uint32_t)buf * ASZB;
        const uint32_t bB = bBase + (uint32_t)buf * BSZB;
#pragma unroll
        for (int ks = 0; ks < 4; ks++) {
            uint32_t af[2][4];
            uint32_t bf[JT][2];
#pragma unroll
            for (int i = 0; i < 2; i++) {
                int sub = lane >> 3, r = lane & 7;
                int row = warpM + i * 16 + (sub & 1) * 8 + r;
                int chunk = ks * 2 + (sub >> 1);
                uint32_t addr =
                    aB + row * 128 + (((uint32_t)chunk ^ (row & 7)) << 4);
                asm volatile(
                    "ldmatrix.sync.aligned.m8n8.x4.shared.b16 {%0,%1,%2,%3}, [%4];"
                    : "=r"(af[i][0]), "=r"(af[i][1]), "=r"(af[i][2]), "=r"(af[i][3])
                    : "r"(addr));
            }
#pragma unroll
            for (int jp = 0; jp < JT / 2; jp++) {
                int r = lane & 7;
                int row = warpN + jp * 16 + ((lane >> 4) & 1) * 8 + r;
                int chunk = ks * 2 + ((lane >> 3) & 1);
                uint32_t addr =
                    bB + row * 128 + (((uint32_t)chunk ^ (row & 7)) << 4);
                asm volatile(
                    "ldmatrix.sync.aligned.m8n8.x4.shared.b16 {%0,%1,%2,%3}, [%4];"
                    : "=r"(bf[2 * jp][0]), "=r"(bf[2 * jp][1]),
                      "=r"(bf[2 * jp + 1][0]), "=r"(bf[2 * jp + 1][1])
                    : "r"(addr));
            }
#pragma unroll
            for (int i = 0; i < 2; i++)
#pragma unroll
                for (int j = 0; j < JT; j++) {
                    asm volatile(
                        "mma.sync.aligned.m16n8k16.row.col.f32.f16.f16.f32 "
                        "{%0,%1,%2,%3}, {%4,%5,%6,%7}, {%8,%9}, {%0,%1,%2,%3};"
                        : "+f"(acc[i][j][0]), "+f"(acc[i][j][1]),
                          "+f"(acc[i][j][2]), "+f"(acc[i][j][3])
                        : "r"(af[i][0]), "r"(af[i][1]), "r"(af[i][2]),
                          "r"(af[i][3]), "r"(bf[j][0]), "r"(bf[j][1]));
                }
        }
    };

    const int nk = K / BK;
    load_stage(0, 0);
    asm volatile("cp.async.commit_group;");
    if (nk > 1) load_stage(1, 1);
    asm volatile("cp.async.commit_group;");

#pragma unroll 1
    for (int t = 0; t < nk; t++) {
        asm volatile("cp.async.wait_group 1;");
        __syncthreads();
        int nt = t + STAGES - 1;
        if (nt < nk) load_stage(nt, nt % STAGES);
        asm volatile("cp.async.commit_group;");
        compute(t % STAGES);
    }

    // epilogue
    const int g  = lane >> 2;
    const int tg = lane & 3;
#pragma unroll
    for (int i = 0; i < 2; i++) {
#pragma unroll
        for (int j = 0; j < JT; j++) {
            int col = bcol + warpN + j * 8 + tg * 2;
            float b0 = 0.f, b1 = 0.f;
            if (bias) { b0 = bias[col]; b1 = bias[col + 1]; }
            int row0 = brow + warpM + i * 16 + g;
            float v0 = acc[i][j][0] * alpha + b0;
            float v1 = acc[i][j][1] * alpha + b1;
            float v2 = acc[i][j][2] * alpha + b0;
            float v3 = acc[i][j][3] * alpha + b1;
            if (relu) {
                v0 = fmaxf(v0, 0.f); v1 = fmaxf(v1, 0.f);
                v2 = fmaxf(v2, 0.f); v3 = fmaxf(v3, 0.f);
            }
            store_pair(&Cg[(long)row0 * ldc + col], v0, v1);
            store_pair(&Cg[(long)(row0 + 8) * ldc + col], v2, v3);
        }
    }
}

// ---------------------------------------------------------------------------
// Final copy x -> d_out (float4)
// ---------------------------------------------------------------------------
__global__ void copy4_kernel(const float4* __restrict__ src,
                             float4* __restrict__ dst, int n4) {
    int i = blockIdx.x * blockDim.x + threadIdx.x;
    if (i < n4) dst[i] = src[i];
}

// ---------------------------------------------------------------------------
// Host launcher
// ---------------------------------------------------------------------------
extern "C" void kernel_launch(void* const* d_in, const int* in_sizes, int n_in,
                              void* d_out, int out_size) {
    const float* enc   = (const float*)d_in[0];
    const float* val_w = (const float*)d_in[1];
    const float* val_b = (const float*)d_in[2];
    const float* pos   = (const float*)d_in[3];
    const float* Wq    = (const float*)d_in[4];
    const float* bq    = (const float*)d_in[5];
    const float* Wk    = (const float*)d_in[6];
    const float* bk    = (const float*)d_in[7];
    const float* Wv    = (const float*)d_in[8];
    const float* bv    = (const float*)d_in[9];
    const float* Wo    = (const float*)d_in[10];
    const float* bo    = (const float*)d_in[11];
    const float* ln1_g = (const float*)d_in[12];
    const float* ln1_b = (const float*)d_in[13];
    const float* c1_w  = (const float*)d_in[14];
    const float* c1_b  = (const float*)d_in[15];
    const float* c2_w  = (const float*)d_in[16];
    const float* c2_b  = (const float*)d_in[17];
    const float* ln2_g = (const float*)d_in[18];
    const float* ln2_b = (const float*)d_in[19];

    float *x, *tmp, *bias3;
    __half *xh, *qkv, *vT, *ctx, *ffn, *attnh, *wTh;
    cudaGetSymbolAddress((void**)&x,     g_x);
    cudaGetSymbolAddress((void**)&tmp,   g_tmp);
    cudaGetSymbolAddress((void**)&bias3, g_bias);
    cudaGetSymbolAddress((void**)&xh,    g_xh);
    cudaGetSymbolAddress((void**)&qkv,   g_qkv);
    cudaGetSymbolAddress((void**)&vT,    g_vT);
    cudaGetSymbolAddress((void**)&ctx,   g_ctx);
    cudaGetSymbolAddress((void**)&ffn,   g_ffn);
    cudaGetSymbolAddress((void**)&attnh, g_attnh);
    cudaGetSymbolAddress((void**)&wTh,   g_wTh);

    constexpr int SMEM128 = 3 * (128 + 128) * 64 * 2;   // 96 KB
    constexpr int SMEM64  = 3 * (128 + 64) * 64 * 2;    // 72 KB
    cudaFuncSetAttribute(hgemm_kernel<128, __half>,
                         cudaFuncAttributeMaxDynamicSharedMemorySize, SMEM128);
    cudaFuncSetAttribute(hgemm_kernel<128, float>,
                         cudaFuncAttributeMaxDynamicSharedMemorySize, SMEM128);
    cudaFuncSetAttribute(hgemm_kernel<64, __half>,
                         cudaFuncAttributeMaxDynamicSharedMemorySize, SMEM64);
    cudaFuncSetAttribute(hgemm_kernel<64, float>,
                         cudaFuncAttributeMaxDynamicSharedMemorySize, SMEM64);

    float* out = (float*)d_out;
    float* attn_all = out + (size_t)B_ * S_ * D_;   // x first, then attns

    {
        dim3 blk(32, 8);
        transpose_attn_kernel<<<dim3(16, 16, 16), blk>>>(Wq, Wk, Wv, Wo,
                                                         wTh + WT_ATTN);
        transpose_c1_kernel<<<dim3(64, 16, 4), blk>>>(c1_w, wTh + WT_C1);
        transpose_c2_kernel<<<dim3(16, 64, 4), blk>>>(c2_w, wTh + WT_C2);
        pack_bias_kernel<<<(3 * L_ * D_ + 255) / 256, 256>>>(bq, bk, bv, bias3);
    }

    embed_kernel<<<(T_ * D_ + 255) / 256, 256>>>(enc, val_w, val_b, pos, x, xh);

    const long TD  = (long)T_ * D_;
    const long SD  = (long)S_ * D_;
    const long SS  = (long)S_ * S_;
    const long HSS = (long)H_ * SS;

    __half* q = qkv;
    __half* k = qkv + TD;
    __half* v = qkv + 2 * TD;

    for (int l = 0; l < L_; l++) {
        const __half* WqkvT = wTh + WT_ATTN + (long)(l * 4) * D_ * D_;
        const __half* WoT   = wTh + WT_ATTN + (long)(l * 4 + 3) * D_ * D_;
        const __half* c1T   = wTh + WT_C1 + (long)l * D_ * F_;   // [F, D]
        const __half* c2T   = wTh + WT_C2 + (long)l * F_ * D_;   // [D, F]
        float* attnL = attn_all + (long)l * B_ * HSS;

        // fused Q/K/V projection (z batches the 3 weight matrices)
        dim3 gQKV(D_ / 128, T_ / 128, 3);
        hgemm_kernel<128, __half><<<gQKV, 256, SMEM128>>>(
            xh, WqkvT, qkv, bias3 + l * D_, D_, D_, D_, D_,
            0, 0, (long)D_ * D_, 0, TD, 0, 1, (long)L_ * D_, 1.f, 0);

        transpose_v_kernel<<<dim3(2, 16, 64), dim3(32, 8)>>>(v, vT);

        // scores = Q_bh @ K_bh^T * scale  (fp32, straight into d_out)
        dim3 gScore(S_ / 128, S_ / 128, B_ * H_);
        hgemm_kernel<128, float><<<gScore, 256, SMEM128>>>(
            q, k, attnL, nullptr, DK_, D_, D_, S_,
            SD, DK_, SD, DK_, HSS, SS, H_, 0, SCALE_, 0);

        softmax512_kernel<<<B_ * H_ * S_, 128>>>(attnL, attnh);

        // ctx = attn @ V_bh  (fp16 in, fp16 out)
        dim3 gCtx(1, S_ / 128, B_ * H_);
        hgemm_kernel<64, __half><<<gCtx, 256, SMEM64>>>(
            attnh, vT, ctx, nullptr, S_, S_, S_, D_,
            HSS, SS, SD, (long)DK_ * S_, SD, DK_, H_, 0, 1.f, 0);

        // out proj (fp32 out for residual) + LN1
        dim3 gOP(D_ / 64, T_ / 128, 1);
        hgemm_kernel<64, float><<<gOP, 256, SMEM64>>>(
            ctx, WoT, tmp, bo + l * D_, D_, D_, D_, D_,
            0, 0, 0, 0, 0, 0, 1, 0, 1.f, 0);
        ln_residual_kernel<<<T_, 128>>>(tmp, x, xh, ln1_g + l * D_,
                                        ln1_b + l * D_);

        // FFN
        dim3 gF1(F_ / 128, T_ / 128, 1);
        hgemm_kernel<128, __half><<<gF1, 256, SMEM128>>>(
            xh, c1T, ffn, c1_b + l * F_, D_, D_, D_, F_,
            0, 0, 0, 0, 0, 0, 1, 0, 1.f, 1);
        dim3 gF2(D_ / 64, T_ / 128, 1);
        hgemm_kernel<64, float><<<gF2, 256, SMEM64>>>(
            ffn, c2T, tmp, c2_b + l * D_, F_, F_, F_, D_,
            0, 0, 0, 0, 0, 0, 1, 0, 1.f, 0);
        ln_residual_kernel<<<T_, 128>>>(tmp, x, xh, ln2_g + l * D_,
                                        ln2_b + l * D_);
    }

    int n4 = T_ * D_ / 4;
    copy4_kernel<<<(n4 + 255) / 256, 256>>>((const float4*)x, (float4*)out, n4);
}